// round 12
// baseline (speedup 1.0000x reference)
#include <cuda_runtime.h>
#include <cuda_fp16.h>
#include <cstdint>

#define NB 4
#define NR 64
#define NC 64
#define NSEQ 16384
#define SLEN 32
#define HD 128
#define NV 30000
#define NVPAD 30080             // 470 * 64
#define PKW 136                 // fp16 pitch of weight/A tiles (272B, LDSM conflict-free)
#define TILE_B (128*PKW*2)      // 34816 bytes per 128x128 fp16 tile
#define TILE_A64 (64*PKW*2)     // 17408 bytes per 64x128 fp16 tile
#define TILE_U4 (TILE_B/16)     // 2176 uint4 per 128-row tile

// ---------------- device scratch ----------------
__device__ float g_PE[(size_t)NVPAD * HD];     // 15.4 MB: embed @ Wi1^T + b1 (L2-resident)
__device__ uint4 g_Wt[4][TILE_U4];             // fp16 pitched tiles: Wi1, Wh1, Wi2, Wh2
__device__ float g_u[NSEQ];
__device__ float g_v[NSEQ];

// ================= helpers =================
__device__ __forceinline__ uint32_t smem_u32(const void* p) {
    uint32_t a;
    asm("{ .reg .u64 t; cvta.to.shared.u64 t, %1; cvt.u32.u64 %0, t; }" : "=r"(a) : "l"(p));
    return a;
}
__device__ __forceinline__ void ldsm_x4(uint32_t* r, uint32_t addr) {
    asm volatile("ldmatrix.sync.aligned.m8n8.x4.shared.b16 {%0,%1,%2,%3}, [%4];"
        : "=r"(r[0]), "=r"(r[1]), "=r"(r[2]), "=r"(r[3]) : "r"(addr));
}
__device__ __forceinline__ void lds128(uint32_t* r, uint32_t addr) {
    asm volatile("ld.shared.v4.b32 {%0,%1,%2,%3}, [%4];"
        : "=r"(r[0]), "=r"(r[1]), "=r"(r[2]), "=r"(r[3]) : "r"(addr));
}
__device__ __forceinline__ void sts128(uint32_t addr, uint32_t r0, uint32_t r1, uint32_t r2, uint32_t r3) {
    asm volatile("st.shared.v4.b32 [%0], {%1,%2,%3,%4};"
        :: "r"(addr), "r"(r0), "r"(r1), "r"(r2), "r"(r3) : "memory");
}
__device__ __forceinline__ void mma_op(float* d, const uint32_t* a, uint32_t b0, uint32_t b1) {
    asm volatile("mma.sync.aligned.m16n8k16.row.col.f32.f16.f16.f32 "
        "{%0,%1,%2,%3}, {%4,%5,%6,%7}, {%8,%9}, {%0,%1,%2,%3};"
        : "+f"(d[0]), "+f"(d[1]), "+f"(d[2]), "+f"(d[3])
        : "r"(a[0]), "r"(a[1]), "r"(a[2]), "r"(a[3]), "r"(b0), "r"(b1));
}
// split (f0,f1) into fp16 hi pair + residual lo pair
__device__ __forceinline__ void split2h(float f0, float f1, uint32_t& hi, uint32_t& lo) {
    __half h0 = __float2half_rn(f0), h1 = __float2half_rn(f1);
    float l0 = f0 - __half2float(h0), l1 = f1 - __half2float(h1);
    __half2 hp = __halves2half2(h0, h1);
    __half2 lp = __halves2half2(__float2half_rn(l0), __float2half_rn(l1));
    hi = *reinterpret_cast<uint32_t*>(&hp);
    lo = *reinterpret_cast<uint32_t*>(&lp);
}
// pack (f0,f1) into a single fp16 pair
__device__ __forceinline__ uint32_t pack2h(float f0, float f1) {
    __half2 hp = __halves2half2(__float2half_rn(f0), __float2half_rn(f1));
    return *reinterpret_cast<uint32_t*>(&hp);
}

// Dual-mtile pass reading A-fragments from per-thread smem state slots:
//   dA/dB: accumulators for mtiles 0/1. hbase: smem addr of this thread's
//   slot (m=0,kc=0) of the state; slot stride 2048 B; m stride 8 slots.
__device__ __forceinline__ void mma_passS(float (*dA)[4], float (*dB)[4],
                                          uint32_t hbase, uint32_t wb,
                                          int lrowB, int lkofB)
{
#pragma unroll
    for (int kc = 0; kc < 8; kc++) {
        uint32_t aA[4], aB[4];
        lds128(aA, hbase + (uint32_t)kc * 2048u);
        lds128(aB, hbase + (uint32_t)(8 + kc) * 2048u);
#pragma unroll
        for (int half = 0; half < 2; half++) {
            uint32_t b[16];
#pragma unroll
            for (int q = 0; q < 4; q++) {
                int ntp = half * 4 + q;
                ldsm_x4(b + 4 * q, wb + (uint32_t)(((ntp * 16 + lrowB) * PKW + kc * 16 + lkofB) * 2));
            }
#pragma unroll
            for (int q = 0; q < 4; q++) {
                int ntp = half * 4 + q;
                mma_op(dA[2 * ntp],     aA, b[4 * q],     b[4 * q + 1]);
                mma_op(dA[2 * ntp + 1], aA, b[4 * q + 2], b[4 * q + 3]);
                mma_op(dB[2 * ntp],     aB, b[4 * q],     b[4 * q + 1]);
                mma_op(dB[2 * ntp + 1], aB, b[4 * q + 2], b[4 * q + 3]);
            }
        }
    }
}

// =========================================================================
// Kernel 0 (prep): convert the 4 weight matrices to fp16 pitched tiles.
// tiles: [0]=Wi1, [1]=Wh1, [2]=Wi2, [3]=Wh2
// =========================================================================
__global__ void __launch_bounds__(256, 8) prep_kernel(
    const float* __restrict__ W_ih, const float* __restrict__ W_hh)
{
    int idx = blockIdx.x * 256 + threadIdx.x;
    if (idx >= 4 * 16384) return;
    int tile = idx >> 14, i = idx & 16383;
    int n = i >> 7, k = i & 127;
    const float* src = (tile == 0) ? W_ih : (tile == 1) ? W_hh
                     : (tile == 2) ? (W_ih + 16384) : (W_hh + 16384);
    reinterpret_cast<__half*>(g_Wt[tile])[n * PKW + k] = __float2half_rn(src[i]);
}

// =========================================================================
// Kernel 1 (PE): PE[v][h] = embed[v] @ Wi1^T + (bi1+bh1)
// 470 CTAs x 128 thr, 64-row tiles, 3 CTAs/SM; embed split hi/lo (2-mult).
// =========================================================================
#define P_AHI 0
#define P_ALO TILE_A64
#define P_B   (2*TILE_A64)
#define P_B1  (2*TILE_A64 + TILE_B)
#define PROJ_SMEM (2*TILE_A64 + TILE_B + 512)

__global__ void __launch_bounds__(128, 3) pe_hmma_kernel(
    const float* __restrict__ embed,
    const float* __restrict__ b_ih, const float* __restrict__ b_hh)
{
    extern __shared__ char smem[];
    const int tid = threadIdx.x;
    const int l = tid & 31, wid = tid >> 5;
    uint32_t sb = smem_u32(smem);

    const int vbase = blockIdx.x * 64;

    // vectorized copy of pre-converted Wi1 tile
    {
        uint4* wdst = (uint4*)(smem + P_B);
        for (int i = tid; i < TILE_U4; i += 128) wdst[i] = g_Wt[0][i];
    }
    ((float*)(smem + P_B1))[tid] = b_ih[tid] + b_hh[tid];
    const float* b1s = (const float*)(smem + P_B1);

    // A tile = 64 consecutive vocab embedding rows (guarded), fp16 hi/lo
    for (int i = tid; i < 64 * 32; i += 128) {
        int r = i >> 5, c = i & 31;
        int vr = vbase + r; if (vr >= NV) vr = NV - 1;
        float4 v = ((const float4*)embed)[(size_t)vr * 32 + c];
        uint32_t h01, l01, h23, l23;
        split2h(v.x, v.y, h01, l01);
        split2h(v.z, v.w, h23, l23);
        uint32_t off = (uint32_t)(r * PKW + 4 * c) * 2;
        *(uint2*)(smem + P_AHI + off) = make_uint2(h01, h23);
        *(uint2*)(smem + P_ALO + off) = make_uint2(l01, l23);
    }
    __syncthreads();

    const int mrow = wid * 16;
    const int lrowB = ((l >> 4) & 1) * 8 + (l & 7);
    const int lkofB = 8 * ((l >> 3) & 1);
    const int lrowA = ((l >> 3) & 1) * 8 + (l & 7);
    const int lkofA = 8 * ((l >> 4) & 1);
    const int g = l >> 2, c2 = (l & 3) * 2;

    float d[16][4];
#pragma unroll
    for (int j = 0; j < 16; j++)
#pragma unroll
        for (int q = 0; q < 4; q++) d[j][q] = 0.f;

    // fused 2-mult pass: B loaded once, A = Ahi + Alo
#pragma unroll
    for (int kc = 0; kc < 8; kc++) {
        uint32_t ah[4], al[4];
        uint32_t aoff = (uint32_t)(((mrow + lrowA) * PKW + kc * 16 + lkofA) * 2);
        ldsm_x4(ah, sb + P_AHI + aoff);
        ldsm_x4(al, sb + P_ALO + aoff);
#pragma unroll
        for (int half = 0; half < 2; half++) {
            uint32_t b[16];
#pragma unroll
            for (int q = 0; q < 4; q++) {
                int ntp = half * 4 + q;
                ldsm_x4(b + 4 * q, sb + P_B + (uint32_t)(((ntp * 16 + lrowB) * PKW + kc * 16 + lkofB) * 2));
            }
#pragma unroll
            for (int q = 0; q < 4; q++) {
                int ntp = half * 4 + q;
                mma_op(d[2 * ntp],     ah, b[4 * q],     b[4 * q + 1]);
                mma_op(d[2 * ntp + 1], ah, b[4 * q + 2], b[4 * q + 3]);
                mma_op(d[2 * ntp],     al, b[4 * q],     b[4 * q + 1]);
                mma_op(d[2 * ntp + 1], al, b[4 * q + 2], b[4 * q + 3]);
            }
        }
    }

    // epilogue: + bias, store to g_PE
    int row0 = vbase + mrow + g;
#pragma unroll
    for (int j = 0; j < 16; j++) {
        float2 bb = *(const float2*)(b1s + 8 * j + c2);
        float* o0 = g_PE + (size_t)row0 * HD + 8 * j + c2;
        *(float2*)o0 = make_float2(d[j][0] + bb.x, d[j][1] + bb.y);
        *(float2*)(o0 + 8 * HD) = make_float2(d[j][2] + bb.x, d[j][3] + bb.y);
    }
}

// =========================================================================
// Kernel 2 (scan): persistent RNN, M=32 seqs/warp, 4 warps/CTA, states in
// per-thread SMEM slots (no barriers in loop). 128 CTAs x 128 thr.
// =========================================================================
#define S_W1  0
#define S_WI  TILE_B
#define S_W2  (2*TILE_B)
#define S_H   (3*TILE_B)                 // 32 slots x 128 thr x 16 B = 64 KB
#define S_B2  (S_H + 65536)
#define S_PW  (S_B2 + 512)
#define SCAN_SMEM (S_PW + 1024)          // ~167.5 KB -> 1 CTA/SM

__global__ void __launch_bounds__(128, 1) scan_hmma_kernel(
    const int* __restrict__ x,
    const float* __restrict__ b_ih, const float* __restrict__ b_hh,
    const float* __restrict__ pred_W)
{
    extern __shared__ char smem[];
    const int tid = threadIdx.x;
    const int l = tid & 31, wid = tid >> 5;
    uint32_t sb = smem_u32(smem);

    // vectorized copy of pre-converted Wh1 / Wi2 / Wh2 tiles
    {
        uint4* wdst = (uint4*)(smem + S_W1);
        for (int i = tid; i < 3 * TILE_U4; i += 128) {
            int t = i / TILE_U4, j = i - t * TILE_U4;
            wdst[t * TILE_U4 + j] = g_Wt[1 + t][j];
        }
    }
    ((float*)(smem + S_B2))[tid] = b_ih[128 + tid] + b_hh[128 + tid];
    ((float*)(smem + S_PW))[tid] = pred_W[tid];
    ((float*)(smem + S_PW))[tid + 128] = pred_W[tid + 128];

    // zero the 32 state slots of this thread (h1: 0..15, h2: 16..31)
    const uint32_t hb1 = sb + S_H + (uint32_t)tid * 16u;          // h1 base
    const uint32_t hb2 = hb1 + 16u * 2048u;                       // h2 base
#pragma unroll
    for (int s = 0; s < 32; s++) sts128(hb1 + (uint32_t)s * 2048u, 0u, 0u, 0u, 0u);
    __syncthreads();

    const int lrowB = ((l >> 4) & 1) * 8 + (l & 7);
    const int lkofB = 8 * ((l >> 3) & 1);
    const int g = l >> 2, c2 = (l & 3) * 2;
    const int mrow = wid * 32;
    const size_t row0 = (size_t)(blockIdx.x * 128 + mrow + g);    // rows row0, +8, +16, +24
    const float* b2s = (const float*)(smem + S_B2);
    const float* pw1 = (const float*)(smem + S_PW);
    const float* pw2 = pw1 + 128;

    const int* xa = x + row0 * SLEN;
    const int* xb = x + (row0 + 8) * SLEN;
    const int* xc = x + (row0 + 16) * SLEN;
    const int* xd = x + (row0 + 24) * SLEN;
    int tokA = xa[0], tokB = xb[0], tokC = xc[0], tokD = xd[0];

    float dA[16][4], dB[16][4];
    float uacc[4] = {0.f, 0.f, 0.f, 0.f};
    float vacc[4] = {0.f, 0.f, 0.f, 0.f};

#pragma unroll 1
    for (int t = 0; t < SLEN; t++) {
        // ---- D init = PE[token] (L2-resident gather; b1 folded into PE) ----
        const float* pa = g_PE + (size_t)tokA * HD;
        const float* pb = g_PE + (size_t)tokB * HD;
        const float* pc = g_PE + (size_t)tokC * HD;
        const float* pd = g_PE + (size_t)tokD * HD;
#pragma unroll
        for (int j = 0; j < 16; j++) {
            float2 v0 = *(const float2*)(pa + 8 * j + c2);
            float2 v1 = *(const float2*)(pb + 8 * j + c2);
            float2 v2 = *(const float2*)(pc + 8 * j + c2);
            float2 v3 = *(const float2*)(pd + 8 * j + c2);
            dA[j][0] = v0.x; dA[j][1] = v0.y; dA[j][2] = v1.x; dA[j][3] = v1.y;
            dB[j][0] = v2.x; dB[j][1] = v2.y; dB[j][2] = v3.x; dB[j][3] = v3.y;
        }
        if (t + 1 < SLEN) {
            tokA = xa[t + 1]; tokB = xb[t + 1]; tokC = xc[t + 1]; tokD = xd[t + 1];
        }

        // ---- layer 1: D += h1 x Wh1 ----
        mma_passS(dA, dB, hb1, sb + S_W1, lrowB, lkofB);

        // ---- epilogue 1: h1 slots = fp16(relu(D)) ----
#pragma unroll
        for (int kc = 0; kc < 8; kc++) {
            int j0 = 2 * kc, j1 = 2 * kc + 1;
            sts128(hb1 + (uint32_t)kc * 2048u,
                   pack2h(fmaxf(dA[j0][0], 0.f), fmaxf(dA[j0][1], 0.f)),
                   pack2h(fmaxf(dA[j0][2], 0.f), fmaxf(dA[j0][3], 0.f)),
                   pack2h(fmaxf(dA[j1][0], 0.f), fmaxf(dA[j1][1], 0.f)),
                   pack2h(fmaxf(dA[j1][2], 0.f), fmaxf(dA[j1][3], 0.f)));
            sts128(hb1 + (uint32_t)(8 + kc) * 2048u,
                   pack2h(fmaxf(dB[j0][0], 0.f), fmaxf(dB[j0][1], 0.f)),
                   pack2h(fmaxf(dB[j0][2], 0.f), fmaxf(dB[j0][3], 0.f)),
                   pack2h(fmaxf(dB[j1][0], 0.f), fmaxf(dB[j1][1], 0.f)),
                   pack2h(fmaxf(dB[j1][2], 0.f), fmaxf(dB[j1][3], 0.f)));
        }

        // ---- layer 2: D = h1 x Wi2 + h2 x Wh2 ----
#pragma unroll
        for (int j = 0; j < 16; j++)
#pragma unroll
            for (int q = 0; q < 4; q++) { dA[j][q] = 0.f; dB[j][q] = 0.f; }
        mma_passS(dA, dB, hb1, sb + S_WI, lrowB, lkofB);
        mma_passS(dA, dB, hb2, sb + S_W2, lrowB, lkofB);

        // ---- epilogue 2: h2 slots = fp16(relu(D + b2)); u/v head at last t ----
#pragma unroll
        for (int kc = 0; kc < 8; kc++) {
            int j0 = 2 * kc, j1 = 2 * kc + 1;
            float2 bb0 = *(const float2*)(b2s + 8 * j0 + c2);
            float2 bb1 = *(const float2*)(b2s + 8 * j1 + c2);
            float fA00 = fmaxf(dA[j0][0] + bb0.x, 0.f), fA01 = fmaxf(dA[j0][1] + bb0.y, 0.f);
            float fA02 = fmaxf(dA[j0][2] + bb0.x, 0.f), fA03 = fmaxf(dA[j0][3] + bb0.y, 0.f);
            float fA10 = fmaxf(dA[j1][0] + bb1.x, 0.f), fA11 = fmaxf(dA[j1][1] + bb1.y, 0.f);
            float fA12 = fmaxf(dA[j1][2] + bb1.x, 0.f), fA13 = fmaxf(dA[j1][3] + bb1.y, 0.f);
            float fB00 = fmaxf(dB[j0][0] + bb0.x, 0.f), fB01 = fmaxf(dB[j0][1] + bb0.y, 0.f);
            float fB02 = fmaxf(dB[j0][2] + bb0.x, 0.f), fB03 = fmaxf(dB[j0][3] + bb0.y, 0.f);
            float fB10 = fmaxf(dB[j1][0] + bb1.x, 0.f), fB11 = fmaxf(dB[j1][1] + bb1.y, 0.f);
            float fB12 = fmaxf(dB[j1][2] + bb1.x, 0.f), fB13 = fmaxf(dB[j1][3] + bb1.y, 0.f);
            sts128(hb2 + (uint32_t)kc * 2048u,
                   pack2h(fA00, fA01), pack2h(fA02, fA03),
                   pack2h(fA10, fA11), pack2h(fA12, fA13));
            sts128(hb2 + (uint32_t)(8 + kc) * 2048u,
                   pack2h(fB00, fB01), pack2h(fB02, fB03),
                   pack2h(fB10, fB11), pack2h(fB12, fB13));
            if (t == SLEN - 1) {
                int c0 = 8 * j0 + c2, c1 = 8 * j1 + c2;
                uacc[0] += pw1[c0] * fA00 + pw1[c0 + 1] * fA01 + pw1[c1] * fA10 + pw1[c1 + 1] * fA11;
                uacc[1] += pw1[c0] * fA02 + pw1[c0 + 1] * fA03 + pw1[c1] * fA12 + pw1[c1 + 1] * fA13;
                uacc[2] += pw1[c0] * fB00 + pw1[c0 + 1] * fB01 + pw1[c1] * fB10 + pw1[c1 + 1] * fB11;
                uacc[3] += pw1[c0] * fB02 + pw1[c0 + 1] * fB03 + pw1[c1] * fB12 + pw1[c1 + 1] * fB13;
                vacc[0] += pw2[c0] * fA00 + pw2[c0 + 1] * fA01 + pw2[c1] * fA10 + pw2[c1 + 1] * fA11;
                vacc[1] += pw2[c0] * fA02 + pw2[c0 + 1] * fA03 + pw2[c1] * fA12 + pw2[c1 + 1] * fA13;
                vacc[2] += pw2[c0] * fB00 + pw2[c0 + 1] * fB01 + pw2[c1] * fB10 + pw2[c1 + 1] * fB11;
                vacc[3] += pw2[c0] * fB02 + pw2[c0 + 1] * fB03 + pw2[c1] * fB12 + pw2[c1 + 1] * fB13;
            }
        }
    }

    // quad reduction over the 4 lanes sharing each row (c2 = 0,2,4,6)
#pragma unroll
    for (int o = 1; o <= 2; o <<= 1) {
#pragma unroll
        for (int q = 0; q < 4; q++) {
            uacc[q] += __shfl_xor_sync(0xffffffffu, uacc[q], o);
            vacc[q] += __shfl_xor_sync(0xffffffffu, vacc[q], o);
        }
    }
    if ((l & 3) == 0) {
#pragma unroll
        for (int q = 0; q < 4; q++) {
            g_u[row0 + 8 * q] = uacc[q];
            g_v[row0 + 8 * q] = vacc[q];
        }
    }
}

// =========================================================================
// Kernel 3: out = u - 2v + rowsum(v) + colsum(v) + pred_b
// grid NB x 1024 thr; warp-per-row/col shuffle reductions; pitch-65 smem.
// =========================================================================
__global__ void __launch_bounds__(1024, 1) reduce2_kernel(
    const float* __restrict__ pred_b, float* __restrict__ out)
{
    __shared__ float vs[64 * 65];
    __shared__ float RS[64], CS[64];
    const int b = blockIdx.x, tid = threadIdx.x;
    const int w = tid >> 5, l = tid & 31;

    for (int i = tid; i < 4096; i += 1024)
        vs[(i >> 6) * 65 + (i & 63)] = g_v[b * 4096 + i];
    __syncthreads();

    // row sums: warp w -> rows w, w+32
    float r0 = vs[w * 65 + l] + vs[w * 65 + l + 32];
    float r1 = vs[(w + 32) * 65 + l] + vs[(w + 32) * 65 + l + 32];
    // col sums: warp w -> cols w, w+32 (pitch 65 => conflict-free)
    float q0 = vs[l * 65 + w] + vs[(l + 32) * 65 + w];
    float q1 = vs[l * 65 + w + 32] + vs[(l + 32) * 65 + w + 32];
#pragma unroll
    for (int o = 16; o; o >>= 1) {
        r0 += __shfl_xor_sync(0xffffffffu, r0, o);
        r1 += __shfl_xor_sync(0xffffffffu, r1, o);
        q0 += __shfl_xor_sync(0xffffffffu, q0, o);
        q1 += __shfl_xor_sync(0xffffffffu, q1, o);
    }
    if (l == 0) { RS[w] = r0; RS[w + 32] = r1; CS[w] = q0; CS[w + 32] = q1; }
    __syncthreads();

    float pb = pred_b[0];
    for (int i = tid; i < 4096; i += 1024) {
        int r = i >> 6, c = i & 63;
        out[b * 4096 + i] =
            g_u[b * 4096 + i] - 2.f * vs[r * 65 + c] + RS[r] + CS[c] + pb;
    }
}

// =========================================================================
extern "C" void kernel_launch(void* const* d_in, const int* in_sizes, int n_in,
                              void* d_out, int out_size)
{
    const int*   x      = (const int*)  d_in[0];
    const float* embed  = (const float*)d_in[1];
    const float* W_ih   = (const float*)d_in[2];
    const float* W_hh   = (const float*)d_in[3];
    const float* b_ih   = (const float*)d_in[4];
    const float* b_hh   = (const float*)d_in[5];
    const float* pred_W = (const float*)d_in[6];
    const float* pred_b = (const float*)d_in[7];
    float* out = (float*)d_out;

    cudaFuncSetAttribute(pe_hmma_kernel,   cudaFuncAttributeMaxDynamicSharedMemorySize, PROJ_SMEM);
    cudaFuncSetAttribute(scan_hmma_kernel, cudaFuncAttributeMaxDynamicSharedMemorySize, SCAN_SMEM);

    prep_kernel<<<256, 256>>>(W_ih, W_hh);
    pe_hmma_kernel<<<NVPAD / 64, 128, PROJ_SMEM>>>(embed, b_ih, b_hh);
    scan_hmma_kernel<<<128, 128, SCAN_SMEM>>>(x, b_ih, b_hh, pred_W);
    reduce2_kernel<<<NB, 1024>>>(pred_b, out);
}

// round 13
// speedup vs baseline: 1.0805x; 1.0805x over previous
#include <cuda_runtime.h>
#include <cuda_fp16.h>
#include <cstdint>

#define NB 4
#define NR 64
#define NC 64
#define NSEQ 16384
#define SLEN 32
#define HD 128
#define NV 30000
#define NVPAD 30080             // 470 * 64
#define PKW 136                 // fp16 pitch of weight/A tiles (272B, LDSM conflict-free)
#define TILE_B (128*PKW*2)      // 34816 bytes per 128x128 fp16 tile
#define TILE_A64 (64*PKW*2)     // 17408 bytes per 64x128 fp16 tile
#define TILE_U4 (TILE_B/16)     // 2176 uint4 per 128-row tile

// ---------------- device scratch ----------------
__device__ float g_PE[(size_t)NVPAD * HD];     // 15.4 MB: embed @ Wi1^T + b1 (L2-resident)
__device__ uint4 g_Wt[4][TILE_U4];             // fp16 pitched tiles: Wi1, Wh1, Wi2, Wh2
__device__ float g_u[NSEQ];
__device__ float g_v[NSEQ];

// ================= helpers =================
__device__ __forceinline__ uint32_t smem_u32(const void* p) {
    uint32_t a;
    asm("{ .reg .u64 t; cvta.to.shared.u64 t, %1; cvt.u32.u64 %0, t; }" : "=r"(a) : "l"(p));
    return a;
}
__device__ __forceinline__ void ldsm_x4(uint32_t* r, uint32_t addr) {
    asm volatile("ldmatrix.sync.aligned.m8n8.x4.shared.b16 {%0,%1,%2,%3}, [%4];"
        : "=r"(r[0]), "=r"(r[1]), "=r"(r[2]), "=r"(r[3]) : "r"(addr));
}
__device__ __forceinline__ void mma_op(float* d, const uint32_t* a, uint32_t b0, uint32_t b1) {
    asm volatile("mma.sync.aligned.m16n8k16.row.col.f32.f16.f16.f32 "
        "{%0,%1,%2,%3}, {%4,%5,%6,%7}, {%8,%9}, {%0,%1,%2,%3};"
        : "+f"(d[0]), "+f"(d[1]), "+f"(d[2]), "+f"(d[3])
        : "r"(a[0]), "r"(a[1]), "r"(a[2]), "r"(a[3]), "r"(b0), "r"(b1));
}
// split (f0,f1) into fp16 hi pair + residual lo pair
__device__ __forceinline__ void split2h(float f0, float f1, uint32_t& hi, uint32_t& lo) {
    __half h0 = __float2half_rn(f0), h1 = __float2half_rn(f1);
    float l0 = f0 - __half2float(h0), l1 = f1 - __half2float(h1);
    __half2 hp = __halves2half2(h0, h1);
    __half2 lp = __halves2half2(__float2half_rn(l0), __float2half_rn(l1));
    hi = *reinterpret_cast<uint32_t*>(&hp);
    lo = *reinterpret_cast<uint32_t*>(&lp);
}
// pack (f0,f1) into a single fp16 pair
__device__ __forceinline__ uint32_t pack2h(float f0, float f1) {
    __half2 hp = __halves2half2(__float2half_rn(f0), __float2half_rn(f1));
    return *reinterpret_cast<uint32_t*>(&hp);
}

// Single-A pass: D += A x B(smem tile at wb)
__device__ __forceinline__ void mma_pass1(float (*d)[4], const uint32_t* a,
                                          uint32_t wb, int lrowB, int lkofB)
{
#pragma unroll
    for (int kc = 0; kc < 8; kc++) {
#pragma unroll
        for (int half = 0; half < 2; half++) {
            uint32_t b[16];
#pragma unroll
            for (int q = 0; q < 4; q++) {
                int ntp = half * 4 + q;
                ldsm_x4(b + 4 * q, wb + (uint32_t)(((ntp * 16 + lrowB) * PKW + kc * 16 + lkofB) * 2));
            }
#pragma unroll
            for (int q = 0; q < 4; q++) {
                int ntp = half * 4 + q;
                mma_op(d[2 * ntp],     a + 4 * kc, b[4 * q],     b[4 * q + 1]);
                mma_op(d[2 * ntp + 1], a + 4 * kc, b[4 * q + 2], b[4 * q + 3]);
            }
        }
    }
}

// =========================================================================
// Kernel 0 (prep): convert the 4 weight matrices to fp16 pitched tiles.
// tiles: [0]=Wi1, [1]=Wh1, [2]=Wi2, [3]=Wh2
// =========================================================================
__global__ void __launch_bounds__(256, 8) prep_kernel(
    const float* __restrict__ W_ih, const float* __restrict__ W_hh)
{
    int idx = blockIdx.x * 256 + threadIdx.x;
    if (idx >= 4 * 16384) return;
    int tile = idx >> 14, i = idx & 16383;
    int n = i >> 7, k = i & 127;
    const float* src = (tile == 0) ? W_ih : (tile == 1) ? W_hh
                     : (tile == 2) ? (W_ih + 16384) : (W_hh + 16384);
    reinterpret_cast<__half*>(g_Wt[tile])[n * PKW + k] = __float2half_rn(src[i]);
}

// =========================================================================
// Kernel 1 (PE): PE[v][h] = embed[v] @ Wi1^T + (bi1+bh1)
// 470 CTAs x 128 thr, 64-row tiles, 3 CTAs/SM; embed split hi/lo (2-mult).
// =========================================================================
#define P_AHI 0
#define P_ALO TILE_A64
#define P_B   (2*TILE_A64)
#define P_B1  (2*TILE_A64 + TILE_B)
#define PROJ_SMEM (2*TILE_A64 + TILE_B + 512)

__global__ void __launch_bounds__(128, 3) pe_hmma_kernel(
    const float* __restrict__ embed,
    const float* __restrict__ b_ih, const float* __restrict__ b_hh)
{
    extern __shared__ char smem[];
    const int tid = threadIdx.x;
    const int l = tid & 31, wid = tid >> 5;
    uint32_t sb = smem_u32(smem);

    const int vbase = blockIdx.x * 64;

    // vectorized copy of pre-converted Wi1 tile
    {
        uint4* wdst = (uint4*)(smem + P_B);
        for (int i = tid; i < TILE_U4; i += 128) wdst[i] = g_Wt[0][i];
    }
    ((float*)(smem + P_B1))[tid] = b_ih[tid] + b_hh[tid];
    const float* b1s = (const float*)(smem + P_B1);

    // A tile = 64 consecutive vocab embedding rows (guarded), fp16 hi/lo
    for (int i = tid; i < 64 * 32; i += 128) {
        int r = i >> 5, c = i & 31;
        int vr = vbase + r; if (vr >= NV) vr = NV - 1;
        float4 v = ((const float4*)embed)[(size_t)vr * 32 + c];
        uint32_t h01, l01, h23, l23;
        split2h(v.x, v.y, h01, l01);
        split2h(v.z, v.w, h23, l23);
        uint32_t off = (uint32_t)(r * PKW + 4 * c) * 2;
        *(uint2*)(smem + P_AHI + off) = make_uint2(h01, h23);
        *(uint2*)(smem + P_ALO + off) = make_uint2(l01, l23);
    }
    __syncthreads();

    const int mrow = wid * 16;
    const int lrowB = ((l >> 4) & 1) * 8 + (l & 7);
    const int lkofB = 8 * ((l >> 3) & 1);
    const int lrowA = ((l >> 3) & 1) * 8 + (l & 7);
    const int lkofA = 8 * ((l >> 4) & 1);
    const int g = l >> 2, c2 = (l & 3) * 2;

    float d[16][4];
#pragma unroll
    for (int j = 0; j < 16; j++)
#pragma unroll
        for (int q = 0; q < 4; q++) d[j][q] = 0.f;

    // fused 2-mult pass: B loaded once, A = Ahi + Alo
#pragma unroll
    for (int kc = 0; kc < 8; kc++) {
        uint32_t ah[4], al[4];
        uint32_t aoff = (uint32_t)(((mrow + lrowA) * PKW + kc * 16 + lkofA) * 2);
        ldsm_x4(ah, sb + P_AHI + aoff);
        ldsm_x4(al, sb + P_ALO + aoff);
#pragma unroll
        for (int half = 0; half < 2; half++) {
            uint32_t b[16];
#pragma unroll
            for (int q = 0; q < 4; q++) {
                int ntp = half * 4 + q;
                ldsm_x4(b + 4 * q, sb + P_B + (uint32_t)(((ntp * 16 + lrowB) * PKW + kc * 16 + lkofB) * 2));
            }
#pragma unroll
            for (int q = 0; q < 4; q++) {
                int ntp = half * 4 + q;
                mma_op(d[2 * ntp],     ah, b[4 * q],     b[4 * q + 1]);
                mma_op(d[2 * ntp + 1], ah, b[4 * q + 2], b[4 * q + 3]);
                mma_op(d[2 * ntp],     al, b[4 * q],     b[4 * q + 1]);
                mma_op(d[2 * ntp + 1], al, b[4 * q + 2], b[4 * q + 3]);
            }
        }
    }

    // epilogue: + bias, store to g_PE
    int row0 = vbase + mrow + g;
#pragma unroll
    for (int j = 0; j < 16; j++) {
        float2 bb = *(const float2*)(b1s + 8 * j + c2);
        float* o0 = g_PE + (size_t)row0 * HD + 8 * j + c2;
        *(float2*)o0 = make_float2(d[j][0] + bb.x, d[j][1] + bb.y);
        *(float2*)(o0 + 8 * HD) = make_float2(d[j][2] + bb.x, d[j][3] + bb.y);
    }
}

// =========================================================================
// Kernel 2 (scan): persistent register-fragment RNN, single-fp16 states
// and weights (3 tile-mults/step), software-pipelined PE gather, fused
// u/v head. 128 CTAs x 256 thr (2 warps/SMSP).
// =========================================================================
#define S_W1  0
#define S_WI  TILE_B
#define S_W2  (2*TILE_B)
#define S_B2  (3*TILE_B)
#define S_PW  (3*TILE_B + 512)
#define SCAN_SMEM (3*TILE_B + 512 + 1024)

__global__ void __launch_bounds__(256, 1) scan_hmma_kernel(
    const int* __restrict__ x,
    const float* __restrict__ b_ih, const float* __restrict__ b_hh,
    const float* __restrict__ pred_W)
{
    extern __shared__ char smem[];
    const int tid = threadIdx.x;
    const int l = tid & 31, wid = tid >> 5;
    uint32_t sb = smem_u32(smem);

    // vectorized copy of pre-converted Wh1 / Wi2 / Wh2 tiles
    {
        uint4* wdst = (uint4*)(smem + S_W1);
        for (int i = tid; i < 3 * TILE_U4; i += 256) {
            int t = i / TILE_U4, j = i - t * TILE_U4;
            wdst[t * TILE_U4 + j] = g_Wt[1 + t][j];
        }
    }
    if (tid < 128) ((float*)(smem + S_B2))[tid] = b_ih[128 + tid] + b_hh[128 + tid];
    if (tid < 256) ((float*)(smem + S_PW))[tid] = pred_W[tid];
    __syncthreads();

    const int lrowB = ((l >> 4) & 1) * 8 + (l & 7);
    const int lkofB = 8 * ((l >> 3) & 1);
    const int g = l >> 2, c2 = (l & 3) * 2;
    const int mrow = wid * 16;
    const size_t rowA = (size_t)(blockIdx.x * 128 + mrow + g);
    const float* b2s = (const float*)(smem + S_B2);
    const float* pw1 = (const float*)(smem + S_PW);
    const float* pw2 = pw1 + 128;

    const int* xa = x + rowA * SLEN;            // tokens of seq rowA
    const int* xb = x + (rowA + 8) * SLEN;      // tokens of seq rowA+8

    uint32_t h1h[32], h2h[32];
#pragma unroll
    for (int i = 0; i < 32; i++) { h1h[i] = 0; h2h[i] = 0; }

    float d[16][4];
    float2 pra[16], prb[16];                     // prefetched PE rows for step t
    float u_a = 0.f, v_a = 0.f, u_b = 0.f, v_b = 0.f;

    // prefetch t=0 PE rows into registers
    {
        int tokA = xa[0], tokB = xb[0];
        const float* pa = g_PE + (size_t)tokA * HD;
        const float* pb = g_PE + (size_t)tokB * HD;
#pragma unroll
        for (int j = 0; j < 16; j++) {
            pra[j] = *(const float2*)(pa + 8 * j + c2);
            prb[j] = *(const float2*)(pb + 8 * j + c2);
        }
    }

#pragma unroll 1
    for (int t = 0; t < SLEN; t++) {
        // ---- D init from prefetched registers ----
#pragma unroll
        for (int j = 0; j < 16; j++) {
            d[j][0] = pra[j].x; d[j][1] = pra[j].y;
            d[j][2] = prb[j].x; d[j][3] = prb[j].y;
        }
        // ---- issue next step's gather now; drains during the MMA passes ----
        if (t + 1 < SLEN) {
            int tokA = xa[t + 1], tokB = xb[t + 1];
            const float* pa = g_PE + (size_t)tokA * HD;
            const float* pb = g_PE + (size_t)tokB * HD;
#pragma unroll
            for (int j = 0; j < 16; j++) {
                pra[j] = *(const float2*)(pa + 8 * j + c2);
                prb[j] = *(const float2*)(pb + 8 * j + c2);
            }
        }

        // ---- layer 1: D += h1 x Wh1 ----
        mma_pass1(d, h1h, sb + S_W1, lrowB, lkofB);

        // ---- epilogue 1: h1 = fp16(relu(D)) ----
#pragma unroll
        for (int kc = 0; kc < 8; kc++) {
            int j0 = 2 * kc, j1 = 2 * kc + 1;
            h1h[4*kc+0] = pack2h(fmaxf(d[j0][0], 0.f), fmaxf(d[j0][1], 0.f));
            h1h[4*kc+1] = pack2h(fmaxf(d[j0][2], 0.f), fmaxf(d[j0][3], 0.f));
            h1h[4*kc+2] = pack2h(fmaxf(d[j1][0], 0.f), fmaxf(d[j1][1], 0.f));
            h1h[4*kc+3] = pack2h(fmaxf(d[j1][2], 0.f), fmaxf(d[j1][3], 0.f));
        }

        // ---- layer 2: D = h1 x Wi2 + h2 x Wh2 ----
#pragma unroll
        for (int j = 0; j < 16; j++)
#pragma unroll
            for (int q = 0; q < 4; q++) d[j][q] = 0.f;
        mma_pass1(d, h1h, sb + S_WI, lrowB, lkofB);
        mma_pass1(d, h2h, sb + S_W2, lrowB, lkofB);

        // ---- epilogue 2: h2 = fp16(relu(D + b2)); fused u/v head at last t ----
#pragma unroll
        for (int kc = 0; kc < 8; kc++) {
            int j0 = 2 * kc, j1 = 2 * kc + 1;
            float2 bb0 = *(const float2*)(b2s + 8 * j0 + c2);
            float2 bb1 = *(const float2*)(b2s + 8 * j1 + c2);
            float f00 = fmaxf(d[j0][0] + bb0.x, 0.f), f01 = fmaxf(d[j0][1] + bb0.y, 0.f);
            float f02 = fmaxf(d[j0][2] + bb0.x, 0.f), f03 = fmaxf(d[j0][3] + bb0.y, 0.f);
            float f10 = fmaxf(d[j1][0] + bb1.x, 0.f), f11 = fmaxf(d[j1][1] + bb1.y, 0.f);
            float f12 = fmaxf(d[j1][2] + bb1.x, 0.f), f13 = fmaxf(d[j1][3] + bb1.y, 0.f);
            h2h[4*kc+0] = pack2h(f00, f01);
            h2h[4*kc+1] = pack2h(f02, f03);
            h2h[4*kc+2] = pack2h(f10, f11);
            h2h[4*kc+3] = pack2h(f12, f13);
            if (t == SLEN - 1) {
                int c0 = 8 * j0 + c2, c1 = 8 * j1 + c2;
                u_a += pw1[c0] * f00 + pw1[c0 + 1] * f01 + pw1[c1] * f10 + pw1[c1 + 1] * f11;
                u_b += pw1[c0] * f02 + pw1[c0 + 1] * f03 + pw1[c1] * f12 + pw1[c1 + 1] * f13;
                v_a += pw2[c0] * f00 + pw2[c0 + 1] * f01 + pw2[c1] * f10 + pw2[c1 + 1] * f11;
                v_b += pw2[c0] * f02 + pw2[c0 + 1] * f03 + pw2[c1] * f12 + pw2[c1 + 1] * f13;
            }
        }
    }

    // quad reduction over the 4 lanes sharing each row (c2 = 0,2,4,6)
#pragma unroll
    for (int o = 1; o <= 2; o <<= 1) {
        u_a += __shfl_xor_sync(0xffffffffu, u_a, o);
        u_b += __shfl_xor_sync(0xffffffffu, u_b, o);
        v_a += __shfl_xor_sync(0xffffffffu, v_a, o);
        v_b += __shfl_xor_sync(0xffffffffu, v_b, o);
    }
    if ((l & 3) == 0) {
        g_u[rowA] = u_a;     g_v[rowA] = v_a;
        g_u[rowA + 8] = u_b; g_v[rowA + 8] = v_b;
    }
}

// =========================================================================
// Kernel 3: out = u - 2v + rowsum(v) + colsum(v) + pred_b
// grid NB x 1024 thr; warp-per-row/col shuffle reductions; pitch-65 smem.
// =========================================================================
__global__ void __launch_bounds__(1024, 1) reduce2_kernel(
    const float* __restrict__ pred_b, float* __restrict__ out)
{
    __shared__ float vs[64 * 65];
    __shared__ float RS[64], CS[64];
    const int b = blockIdx.x, tid = threadIdx.x;
    const int w = tid >> 5, l = tid & 31;

    for (int i = tid; i < 4096; i += 1024)
        vs[(i >> 6) * 65 + (i & 63)] = g_v[b * 4096 + i];
    __syncthreads();

    // row sums: warp w -> rows w, w+32
    float r0 = vs[w * 65 + l] + vs[w * 65 + l + 32];
    float r1 = vs[(w + 32) * 65 + l] + vs[(w + 32) * 65 + l + 32];
    // col sums: warp w -> cols w, w+32 (pitch 65 => conflict-free)
    float q0 = vs[l * 65 + w] + vs[(l + 32) * 65 + w];
    float q1 = vs[l * 65 + w + 32] + vs[(l + 32) * 65 + w + 32];
#pragma unroll
    for (int o = 16; o; o >>= 1) {
        r0 += __shfl_xor_sync(0xffffffffu, r0, o);
        r1 += __shfl_xor_sync(0xffffffffu, r1, o);
        q0 += __shfl_xor_sync(0xffffffffu, q0, o);
        q1 += __shfl_xor_sync(0xffffffffu, q1, o);
    }
    if (l == 0) { RS[w] = r0; RS[w + 32] = r1; CS[w] = q0; CS[w + 32] = q1; }
    __syncthreads();

    float pb = pred_b[0];
    for (int i = tid; i < 4096; i += 1024) {
        int r = i >> 6, c = i & 63;
        out[b * 4096 + i] =
            g_u[b * 4096 + i] - 2.f * vs[r * 65 + c] + RS[r] + CS[c] + pb;
    }
}

// =========================================================================
extern "C" void kernel_launch(void* const* d_in, const int* in_sizes, int n_in,
                              void* d_out, int out_size)
{
    const int*   x      = (const int*)  d_in[0];
    const float* embed  = (const float*)d_in[1];
    const float* W_ih   = (const float*)d_in[2];
    const float* W_hh   = (const float*)d_in[3];
    const float* b_ih   = (const float*)d_in[4];
    const float* b_hh   = (const float*)d_in[5];
    const float* pred_W = (const float*)d_in[6];
    const float* pred_b = (const float*)d_in[7];
    float* out = (float*)d_out;

    cudaFuncSetAttribute(pe_hmma_kernel,   cudaFuncAttributeMaxDynamicSharedMemorySize, PROJ_SMEM);
    cudaFuncSetAttribute(scan_hmma_kernel, cudaFuncAttributeMaxDynamicSharedMemorySize, SCAN_SMEM);

    prep_kernel<<<256, 256>>>(W_ih, W_hh);
    pe_hmma_kernel<<<NVPAD / 64, 128, PROJ_SMEM>>>(embed, b_ih, b_hh);
    scan_hmma_kernel<<<128, 256, SCAN_SMEM>>>(x, b_ih, b_hh, pred_W);
    reduce2_kernel<<<NB, 1024>>>(pred_b, out);
}

// round 14
// speedup vs baseline: 1.1286x; 1.0446x over previous
#include <cuda_runtime.h>
#include <cuda_fp16.h>
#include <cstdint>

#define NB 4
#define NR 64
#define NC 64
#define NSEQ 16384
#define SLEN 32
#define HD 128
#define NV 30000
#define NVPAD 30080             // 235 * 128
#define PKW 136                 // fp16 pitch of weight/A tiles (272B, LDSM conflict-free)
#define TILE_B (128*PKW*2)      // 34816 bytes per 128x128 fp16 tile
#define TILE_U4 (TILE_B/16)     // 2176 uint4 per 128-row tile

// ---------------- device scratch ----------------
__device__ float g_PE[(size_t)NVPAD * HD];     // 15.4 MB: embed @ Wi1^T + b1 (L2-resident)
__device__ uint4 g_Wt[4][TILE_U4];             // fp16 pitched tiles: Wi1, Wh1, Wi2, Wh2
__device__ float g_u[NSEQ];
__device__ float g_v[NSEQ];

// ================= helpers =================
__device__ __forceinline__ uint32_t smem_u32(const void* p) {
    uint32_t a;
    asm("{ .reg .u64 t; cvta.to.shared.u64 t, %1; cvt.u32.u64 %0, t; }" : "=r"(a) : "l"(p));
    return a;
}
__device__ __forceinline__ void ldsm_x4(uint32_t* r, uint32_t addr) {
    asm volatile("ldmatrix.sync.aligned.m8n8.x4.shared.b16 {%0,%1,%2,%3}, [%4];"
        : "=r"(r[0]), "=r"(r[1]), "=r"(r[2]), "=r"(r[3]) : "r"(addr));
}
__device__ __forceinline__ void mma_op(float* d, const uint32_t* a, uint32_t b0, uint32_t b1) {
    asm volatile("mma.sync.aligned.m16n8k16.row.col.f32.f16.f16.f32 "
        "{%0,%1,%2,%3}, {%4,%5,%6,%7}, {%8,%9}, {%0,%1,%2,%3};"
        : "+f"(d[0]), "+f"(d[1]), "+f"(d[2]), "+f"(d[3])
        : "r"(a[0]), "r"(a[1]), "r"(a[2]), "r"(a[3]), "r"(b0), "r"(b1));
}
// split (f0,f1) into fp16 hi pair + residual lo pair
__device__ __forceinline__ void split2h(float f0, float f1, uint32_t& hi, uint32_t& lo) {
    __half h0 = __float2half_rn(f0), h1 = __float2half_rn(f1);
    float l0 = f0 - __half2float(h0), l1 = f1 - __half2float(h1);
    __half2 hp = __halves2half2(h0, h1);
    __half2 lp = __halves2half2(__float2half_rn(l0), __float2half_rn(l1));
    hi = *reinterpret_cast<uint32_t*>(&hp);
    lo = *reinterpret_cast<uint32_t*>(&lp);
}
// pack (f0,f1) into a single fp16 pair
__device__ __forceinline__ uint32_t pack2h(float f0, float f1) {
    __half2 hp = __halves2half2(__float2half_rn(f0), __float2half_rn(f1));
    return *reinterpret_cast<uint32_t*>(&hp);
}

// Single-A pass: D += A x B(smem tile at wb)
__device__ __forceinline__ void mma_pass1(float (*d)[4], const uint32_t* a,
                                          uint32_t wb, int lrowB, int lkofB)
{
#pragma unroll
    for (int kc = 0; kc < 8; kc++) {
#pragma unroll
        for (int half = 0; half < 2; half++) {
            uint32_t b[16];
#pragma unroll
            for (int q = 0; q < 4; q++) {
                int ntp = half * 4 + q;
                ldsm_x4(b + 4 * q, wb + (uint32_t)(((ntp * 16 + lrowB) * PKW + kc * 16 + lkofB) * 2));
            }
#pragma unroll
            for (int q = 0; q < 4; q++) {
                int ntp = half * 4 + q;
                mma_op(d[2 * ntp],     a + 4 * kc, b[4 * q],     b[4 * q + 1]);
                mma_op(d[2 * ntp + 1], a + 4 * kc, b[4 * q + 2], b[4 * q + 3]);
            }
        }
    }
}

// =========================================================================
// Kernel 0 (prep): convert the 4 weight matrices to fp16 pitched tiles.
// tiles: [0]=Wi1, [1]=Wh1, [2]=Wi2, [3]=Wh2
// =========================================================================
__global__ void __launch_bounds__(256, 8) prep_kernel(
    const float* __restrict__ W_ih, const float* __restrict__ W_hh)
{
    int idx = blockIdx.x * 256 + threadIdx.x;
    if (idx >= 4 * 16384) return;
    int tile = idx >> 14, i = idx & 16383;
    int n = i >> 7, k = i & 127;
    const float* src = (tile == 0) ? W_ih : (tile == 1) ? W_hh
                     : (tile == 2) ? (W_ih + 16384) : (W_hh + 16384);
    reinterpret_cast<__half*>(g_Wt[tile])[n * PKW + k] = __float2half_rn(src[i]);
}

// =========================================================================
// Kernel 1 (PE): PE[v][h] = embed[v] @ Wi1^T + (bi1+bh1)
// 235 CTAs x 256 thr, 128-row tiles, 2 CTAs/SM; embed split hi/lo (2-mult).
// =========================================================================
#define P_AHI 0
#define P_ALO TILE_B
#define P_B   (2*TILE_B)
#define P_B1  (3*TILE_B)
#define PROJ_SMEM (3*TILE_B + 512)

__global__ void __launch_bounds__(256, 2) pe_hmma_kernel(
    const float* __restrict__ embed,
    const float* __restrict__ b_ih, const float* __restrict__ b_hh)
{
    extern __shared__ char smem[];
    const int tid = threadIdx.x;
    const int l = tid & 31, wid = tid >> 5;
    uint32_t sb = smem_u32(smem);

    const int vbase = blockIdx.x * 128;

    // vectorized copy of pre-converted Wi1 tile
    {
        uint4* wdst = (uint4*)(smem + P_B);
        for (int i = tid; i < TILE_U4; i += 256) wdst[i] = g_Wt[0][i];
    }
    if (tid < 128) ((float*)(smem + P_B1))[tid] = b_ih[tid] + b_hh[tid];
    const float* b1s = (const float*)(smem + P_B1);

    // A tile = 128 consecutive vocab embedding rows (guarded), fp16 hi/lo
    for (int i = tid; i < 128 * 32; i += 256) {
        int r = i >> 5, c = i & 31;
        int vr = vbase + r; if (vr >= NV) vr = NV - 1;
        float4 v = ((const float4*)embed)[(size_t)vr * 32 + c];
        uint32_t h01, l01, h23, l23;
        split2h(v.x, v.y, h01, l01);
        split2h(v.z, v.w, h23, l23);
        uint32_t off = (uint32_t)(r * PKW + 4 * c) * 2;
        *(uint2*)(smem + P_AHI + off) = make_uint2(h01, h23);
        *(uint2*)(smem + P_ALO + off) = make_uint2(l01, l23);
    }
    __syncthreads();

    const int mrow = wid * 16;
    const int lrowB = ((l >> 4) & 1) * 8 + (l & 7);
    const int lkofB = 8 * ((l >> 3) & 1);
    const int lrowA = ((l >> 3) & 1) * 8 + (l & 7);
    const int lkofA = 8 * ((l >> 4) & 1);
    const int g = l >> 2, c2 = (l & 3) * 2;

    float d[16][4];
#pragma unroll
    for (int j = 0; j < 16; j++)
#pragma unroll
        for (int q = 0; q < 4; q++) d[j][q] = 0.f;

    // fused 2-mult pass: B loaded once, A = Ahi + Alo
#pragma unroll
    for (int kc = 0; kc < 8; kc++) {
        uint32_t ah[4], al[4];
        uint32_t aoff = (uint32_t)(((mrow + lrowA) * PKW + kc * 16 + lkofA) * 2);
        ldsm_x4(ah, sb + P_AHI + aoff);
        ldsm_x4(al, sb + P_ALO + aoff);
#pragma unroll
        for (int half = 0; half < 2; half++) {
            uint32_t b[16];
#pragma unroll
            for (int q = 0; q < 4; q++) {
                int ntp = half * 4 + q;
                ldsm_x4(b + 4 * q, sb + P_B + (uint32_t)(((ntp * 16 + lrowB) * PKW + kc * 16 + lkofB) * 2));
            }
#pragma unroll
            for (int q = 0; q < 4; q++) {
                int ntp = half * 4 + q;
                mma_op(d[2 * ntp],     ah, b[4 * q],     b[4 * q + 1]);
                mma_op(d[2 * ntp + 1], ah, b[4 * q + 2], b[4 * q + 3]);
                mma_op(d[2 * ntp],     al, b[4 * q],     b[4 * q + 1]);
                mma_op(d[2 * ntp + 1], al, b[4 * q + 2], b[4 * q + 3]);
            }
        }
    }

    // epilogue: + bias, store to g_PE
    int row0 = vbase + mrow + g;
#pragma unroll
    for (int j = 0; j < 16; j++) {
        float2 bb = *(const float2*)(b1s + 8 * j + c2);
        float* o0 = g_PE + (size_t)row0 * HD + 8 * j + c2;
        *(float2*)o0 = make_float2(d[j][0] + bb.x, d[j][1] + bb.y);
        *(float2*)(o0 + 8 * HD) = make_float2(d[j][2] + bb.x, d[j][3] + bb.y);
    }
}

// =========================================================================
// Kernel 2 (scan): persistent register-fragment RNN, single-fp16 states
// and weights (3 tile-mults/step), software-pipelined PE gather, fused
// u/v head. 128 CTAs x 256 thr (2 warps/SMSP).
// =========================================================================
#define S_W1  0
#define S_WI  TILE_B
#define S_W2  (2*TILE_B)
#define S_B2  (3*TILE_B)
#define S_PW  (3*TILE_B + 512)
#define SCAN_SMEM (3*TILE_B + 512 + 1024)

__global__ void __launch_bounds__(256, 1) scan_hmma_kernel(
    const int* __restrict__ x,
    const float* __restrict__ b_ih, const float* __restrict__ b_hh,
    const float* __restrict__ pred_W)
{
    extern __shared__ char smem[];
    const int tid = threadIdx.x;
    const int l = tid & 31, wid = tid >> 5;
    uint32_t sb = smem_u32(smem);

    // vectorized copy of pre-converted Wh1 / Wi2 / Wh2 tiles
    {
        uint4* wdst = (uint4*)(smem + S_W1);
        for (int i = tid; i < 3 * TILE_U4; i += 256) {
            int t = i / TILE_U4, j = i - t * TILE_U4;
            wdst[t * TILE_U4 + j] = g_Wt[1 + t][j];
        }
    }
    if (tid < 128) ((float*)(smem + S_B2))[tid] = b_ih[128 + tid] + b_hh[128 + tid];
    if (tid < 256) ((float*)(smem + S_PW))[tid] = pred_W[tid];
    __syncthreads();

    const int lrowB = ((l >> 4) & 1) * 8 + (l & 7);
    const int lkofB = 8 * ((l >> 3) & 1);
    const int g = l >> 2, c2 = (l & 3) * 2;
    const int mrow = wid * 16;
    const size_t rowA = (size_t)(blockIdx.x * 128 + mrow + g);
    const float* b2s = (const float*)(smem + S_B2);
    const float* pw1 = (const float*)(smem + S_PW);
    const float* pw2 = pw1 + 128;

    const int* xa = x + rowA * SLEN;            // tokens of seq rowA
    const int* xb = x + (rowA + 8) * SLEN;      // tokens of seq rowA+8

    uint32_t h1h[32], h2h[32];
#pragma unroll
    for (int i = 0; i < 32; i++) { h1h[i] = 0; h2h[i] = 0; }

    float d[16][4];
    float2 pra[16], prb[16];                     // prefetched PE rows for step t
    float u_a = 0.f, v_a = 0.f, u_b = 0.f, v_b = 0.f;

    // prefetch t=0 PE rows into registers
    {
        int tokA = xa[0], tokB = xb[0];
        const float* pa = g_PE + (size_t)tokA * HD;
        const float* pb = g_PE + (size_t)tokB * HD;
#pragma unroll
        for (int j = 0; j < 16; j++) {
            pra[j] = *(const float2*)(pa + 8 * j + c2);
            prb[j] = *(const float2*)(pb + 8 * j + c2);
        }
    }

#pragma unroll 1
    for (int t = 0; t < SLEN; t++) {
        // ---- D init from prefetched registers ----
#pragma unroll
        for (int j = 0; j < 16; j++) {
            d[j][0] = pra[j].x; d[j][1] = pra[j].y;
            d[j][2] = prb[j].x; d[j][3] = prb[j].y;
        }
        // ---- issue next step's gather now; drains during the MMA passes ----
        if (t + 1 < SLEN) {
            int tokA = xa[t + 1], tokB = xb[t + 1];
            const float* pa = g_PE + (size_t)tokA * HD;
            const float* pb = g_PE + (size_t)tokB * HD;
#pragma unroll
            for (int j = 0; j < 16; j++) {
                pra[j] = *(const float2*)(pa + 8 * j + c2);
                prb[j] = *(const float2*)(pb + 8 * j + c2);
            }
        }

        // ---- layer 1: D += h1 x Wh1 ----
        mma_pass1(d, h1h, sb + S_W1, lrowB, lkofB);

        // ---- epilogue 1: h1 = fp16(relu(D)) ----
#pragma unroll
        for (int kc = 0; kc < 8; kc++) {
            int j0 = 2 * kc, j1 = 2 * kc + 1;
            h1h[4*kc+0] = pack2h(fmaxf(d[j0][0], 0.f), fmaxf(d[j0][1], 0.f));
            h1h[4*kc+1] = pack2h(fmaxf(d[j0][2], 0.f), fmaxf(d[j0][3], 0.f));
            h1h[4*kc+2] = pack2h(fmaxf(d[j1][0], 0.f), fmaxf(d[j1][1], 0.f));
            h1h[4*kc+3] = pack2h(fmaxf(d[j1][2], 0.f), fmaxf(d[j1][3], 0.f));
        }

        // ---- layer 2: D = h1 x Wi2 + h2 x Wh2 ----
#pragma unroll
        for (int j = 0; j < 16; j++)
#pragma unroll
            for (int q = 0; q < 4; q++) d[j][q] = 0.f;
        mma_pass1(d, h1h, sb + S_WI, lrowB, lkofB);
        mma_pass1(d, h2h, sb + S_W2, lrowB, lkofB);

        // ---- epilogue 2: h2 = fp16(relu(D + b2)); fused u/v head at last t ----
#pragma unroll
        for (int kc = 0; kc < 8; kc++) {
            int j0 = 2 * kc, j1 = 2 * kc + 1;
            float2 bb0 = *(const float2*)(b2s + 8 * j0 + c2);
            float2 bb1 = *(const float2*)(b2s + 8 * j1 + c2);
            float f00 = fmaxf(d[j0][0] + bb0.x, 0.f), f01 = fmaxf(d[j0][1] + bb0.y, 0.f);
            float f02 = fmaxf(d[j0][2] + bb0.x, 0.f), f03 = fmaxf(d[j0][3] + bb0.y, 0.f);
            float f10 = fmaxf(d[j1][0] + bb1.x, 0.f), f11 = fmaxf(d[j1][1] + bb1.y, 0.f);
            float f12 = fmaxf(d[j1][2] + bb1.x, 0.f), f13 = fmaxf(d[j1][3] + bb1.y, 0.f);
            h2h[4*kc+0] = pack2h(f00, f01);
            h2h[4*kc+1] = pack2h(f02, f03);
            h2h[4*kc+2] = pack2h(f10, f11);
            h2h[4*kc+3] = pack2h(f12, f13);
            if (t == SLEN - 1) {
                int c0 = 8 * j0 + c2, c1 = 8 * j1 + c2;
                u_a += pw1[c0] * f00 + pw1[c0 + 1] * f01 + pw1[c1] * f10 + pw1[c1 + 1] * f11;
                u_b += pw1[c0] * f02 + pw1[c0 + 1] * f03 + pw1[c1] * f12 + pw1[c1 + 1] * f13;
                v_a += pw2[c0] * f00 + pw2[c0 + 1] * f01 + pw2[c1] * f10 + pw2[c1 + 1] * f11;
                v_b += pw2[c0] * f02 + pw2[c0 + 1] * f03 + pw2[c1] * f12 + pw2[c1 + 1] * f13;
            }
        }
    }

    // quad reduction over the 4 lanes sharing each row (c2 = 0,2,4,6)
#pragma unroll
    for (int o = 1; o <= 2; o <<= 1) {
        u_a += __shfl_xor_sync(0xffffffffu, u_a, o);
        u_b += __shfl_xor_sync(0xffffffffu, u_b, o);
        v_a += __shfl_xor_sync(0xffffffffu, v_a, o);
        v_b += __shfl_xor_sync(0xffffffffu, v_b, o);
    }
    if ((l & 3) == 0) {
        g_u[rowA] = u_a;     g_v[rowA] = v_a;
        g_u[rowA + 8] = u_b; g_v[rowA + 8] = v_b;
    }
}

// =========================================================================
// Kernel 3: out = u - 2v + rowsum(v) + colsum(v) + pred_b
// grid NB x 1024 thr; warp-per-row/col shuffle reductions; pitch-65 smem.
// =========================================================================
__global__ void __launch_bounds__(1024, 1) reduce2_kernel(
    const float* __restrict__ pred_b, float* __restrict__ out)
{
    __shared__ float vs[64 * 65];
    __shared__ float RS[64], CS[64];
    const int b = blockIdx.x, tid = threadIdx.x;
    const int w = tid >> 5, l = tid & 31;

    for (int i = tid; i < 4096; i += 1024)
        vs[(i >> 6) * 65 + (i & 63)] = g_v[b * 4096 + i];
    __syncthreads();

    // row sums: warp w -> rows w, w+32
    float r0 = vs[w * 65 + l] + vs[w * 65 + l + 32];
    float r1 = vs[(w + 32) * 65 + l] + vs[(w + 32) * 65 + l + 32];
    // col sums: warp w -> cols w, w+32 (pitch 65 => conflict-free)
    float q0 = vs[l * 65 + w] + vs[(l + 32) * 65 + w];
    float q1 = vs[l * 65 + w + 32] + vs[(l + 32) * 65 + w + 32];
#pragma unroll
    for (int o = 16; o; o >>= 1) {
        r0 += __shfl_xor_sync(0xffffffffu, r0, o);
        r1 += __shfl_xor_sync(0xffffffffu, r1, o);
        q0 += __shfl_xor_sync(0xffffffffu, q0, o);
        q1 += __shfl_xor_sync(0xffffffffu, q1, o);
    }
    if (l == 0) { RS[w] = r0; RS[w + 32] = r1; CS[w] = q0; CS[w + 32] = q1; }
    __syncthreads();

    float pb = pred_b[0];
    for (int i = tid; i < 4096; i += 1024) {
        int r = i >> 6, c = i & 63;
        out[b * 4096 + i] =
            g_u[b * 4096 + i] - 2.f * vs[r * 65 + c] + RS[r] + CS[c] + pb;
    }
}

// =========================================================================
extern "C" void kernel_launch(void* const* d_in, const int* in_sizes, int n_in,
                              void* d_out, int out_size)
{
    const int*   x      = (const int*)  d_in[0];
    const float* embed  = (const float*)d_in[1];
    const float* W_ih   = (const float*)d_in[2];
    const float* W_hh   = (const float*)d_in[3];
    const float* b_ih   = (const float*)d_in[4];
    const float* b_hh   = (const float*)d_in[5];
    const float* pred_W = (const float*)d_in[6];
    const float* pred_b = (const float*)d_in[7];
    float* out = (float*)d_out;

    cudaFuncSetAttribute(pe_hmma_kernel,   cudaFuncAttributeMaxDynamicSharedMemorySize, PROJ_SMEM);
    cudaFuncSetAttribute(scan_hmma_kernel, cudaFuncAttributeMaxDynamicSharedMemorySize, SCAN_SMEM);

    prep_kernel<<<256, 256>>>(W_ih, W_hh);
    pe_hmma_kernel<<<NVPAD / 128, 256, PROJ_SMEM>>>(embed, b_ih, b_hh);
    scan_hmma_kernel<<<128, 256, SCAN_SMEM>>>(x, b_ih, b_hh, pred_W);
    reduce2_kernel<<<NB, 1024>>>(pred_b, out);
}

// round 15
// speedup vs baseline: 1.1419x; 1.0117x over previous
#include <cuda_runtime.h>
#include <cuda_fp16.h>
#include <cstdint>

#define NB 4
#define NR 64
#define NC 64
#define NSEQ 16384
#define SLEN 32
#define HD 128
#define NV 30000
#define NVPAD 30080             // 235 * 128
#define PKW 136                 // fp16 pitch of weight/A tiles (272B, LDSM conflict-free)
#define TILE_B (128*PKW*2)      // 34816 bytes per 128x128 fp16 tile
#define TILE_U4 (TILE_B/16)     // 2176 uint4 per 128-row tile

// ---------------- device scratch ----------------
__device__ float g_PE[(size_t)NVPAD * HD];     // 15.4 MB: embed @ Wi1^T + b1 (L2-resident)
__device__ uint4 g_Wt[4][TILE_U4];             // fp16 pitched tiles: Wi1, Wh1, Wi2, Wh2
__device__ float g_u[NSEQ];
__device__ float g_v[NSEQ];

// ================= helpers =================
__device__ __forceinline__ uint32_t smem_u32(const void* p) {
    uint32_t a;
    asm("{ .reg .u64 t; cvta.to.shared.u64 t, %1; cvt.u32.u64 %0, t; }" : "=r"(a) : "l"(p));
    return a;
}
__device__ __forceinline__ void ldsm_x4(uint32_t* r, uint32_t addr) {
    asm volatile("ldmatrix.sync.aligned.m8n8.x4.shared.b16 {%0,%1,%2,%3}, [%4];"
        : "=r"(r[0]), "=r"(r[1]), "=r"(r[2]), "=r"(r[3]) : "r"(addr));
}
__device__ __forceinline__ void mma_op(float* d, const uint32_t* a, uint32_t b0, uint32_t b1) {
    asm volatile("mma.sync.aligned.m16n8k16.row.col.f32.f16.f16.f32 "
        "{%0,%1,%2,%3}, {%4,%5,%6,%7}, {%8,%9}, {%0,%1,%2,%3};"
        : "+f"(d[0]), "+f"(d[1]), "+f"(d[2]), "+f"(d[3])
        : "r"(a[0]), "r"(a[1]), "r"(a[2]), "r"(a[3]), "r"(b0), "r"(b1));
}
// pack (f0,f1) into fp16 pair (f0 -> lo) using single-instr packed cvt
__device__ __forceinline__ uint32_t pack2h(float f0, float f1) {
    uint32_t r;
    asm("cvt.rn.f16x2.f32 %0, %1, %2;" : "=r"(r) : "f"(f1), "f"(f0));
    return r;
}

// Single-A pass: D += A x B(smem tile at wb)
__device__ __forceinline__ void mma_pass1(float (*d)[4], const uint32_t* a,
                                          uint32_t wb, int lrowB, int lkofB)
{
#pragma unroll
    for (int kc = 0; kc < 8; kc++) {
#pragma unroll
        for (int half = 0; half < 2; half++) {
            uint32_t b[16];
#pragma unroll
            for (int q = 0; q < 4; q++) {
                int ntp = half * 4 + q;
                ldsm_x4(b + 4 * q, wb + (uint32_t)(((ntp * 16 + lrowB) * PKW + kc * 16 + lkofB) * 2));
            }
#pragma unroll
            for (int q = 0; q < 4; q++) {
                int ntp = half * 4 + q;
                mma_op(d[2 * ntp],     a + 4 * kc, b[4 * q],     b[4 * q + 1]);
                mma_op(d[2 * ntp + 1], a + 4 * kc, b[4 * q + 2], b[4 * q + 3]);
            }
        }
    }
}

// =========================================================================
// Kernel 0 (prep): convert the 4 weight matrices to fp16 pitched tiles.
// tiles: [0]=Wi1, [1]=Wh1, [2]=Wi2, [3]=Wh2
// =========================================================================
__global__ void __launch_bounds__(256, 8) prep_kernel(
    const float* __restrict__ W_ih, const float* __restrict__ W_hh)
{
    int idx = blockIdx.x * 256 + threadIdx.x;
    if (idx >= 4 * 16384) return;
    int tile = idx >> 14, i = idx & 16383;
    int n = i >> 7, k = i & 127;
    const float* src = (tile == 0) ? W_ih : (tile == 1) ? W_hh
                     : (tile == 2) ? (W_ih + 16384) : (W_hh + 16384);
    reinterpret_cast<__half*>(g_Wt[tile])[n * PKW + k] = __float2half_rn(src[i]);
}

// =========================================================================
// Kernel 1 (PE): PE[v][h] = embed[v] @ Wi1^T + (bi1+bh1)
// 235 CTAs x 256 thr, 128-row tiles, single fp16 A (no compensation).
// =========================================================================
#define P_A   0
#define P_B   TILE_B
#define P_B1  (2*TILE_B)
#define PROJ_SMEM (2*TILE_B + 512)

__global__ void __launch_bounds__(256, 2) pe_hmma_kernel(
    const float* __restrict__ embed,
    const float* __restrict__ b_ih, const float* __restrict__ b_hh)
{
    extern __shared__ char smem[];
    const int tid = threadIdx.x;
    const int l = tid & 31, wid = tid >> 5;
    uint32_t sb = smem_u32(smem);

    const int vbase = blockIdx.x * 128;

    // vectorized copy of pre-converted Wi1 tile
    {
        uint4* wdst = (uint4*)(smem + P_B);
        for (int i = tid; i < TILE_U4; i += 256) wdst[i] = g_Wt[0][i];
    }
    if (tid < 128) ((float*)(smem + P_B1))[tid] = b_ih[tid] + b_hh[tid];
    const float* b1s = (const float*)(smem + P_B1);

    // A tile = 128 consecutive vocab embedding rows (guarded), single fp16
    for (int i = tid; i < 128 * 32; i += 256) {
        int r = i >> 5, c = i & 31;
        int vr = vbase + r; if (vr >= NV) vr = NV - 1;
        float4 v = ((const float4*)embed)[(size_t)vr * 32 + c];
        uint32_t off = (uint32_t)(r * PKW + 4 * c) * 2;
        *(uint2*)(smem + P_A + off) = make_uint2(pack2h(v.x, v.y), pack2h(v.z, v.w));
    }
    __syncthreads();

    const int mrow = wid * 16;
    const int lrowB = ((l >> 4) & 1) * 8 + (l & 7);
    const int lkofB = 8 * ((l >> 3) & 1);
    const int lrowA = ((l >> 3) & 1) * 8 + (l & 7);
    const int lkofA = 8 * ((l >> 4) & 1);
    const int g = l >> 2, c2 = (l & 3) * 2;

    float d[16][4];
#pragma unroll
    for (int j = 0; j < 16; j++)
#pragma unroll
        for (int q = 0; q < 4; q++) d[j][q] = 0.f;

    // single pass: D = A x B
#pragma unroll
    for (int kc = 0; kc < 8; kc++) {
        uint32_t ah[4];
        ldsm_x4(ah, sb + P_A + (uint32_t)(((mrow + lrowA) * PKW + kc * 16 + lkofA) * 2));
#pragma unroll
        for (int half = 0; half < 2; half++) {
            uint32_t b[16];
#pragma unroll
            for (int q = 0; q < 4; q++) {
                int ntp = half * 4 + q;
                ldsm_x4(b + 4 * q, sb + P_B + (uint32_t)(((ntp * 16 + lrowB) * PKW + kc * 16 + lkofB) * 2));
            }
#pragma unroll
            for (int q = 0; q < 4; q++) {
                int ntp = half * 4 + q;
                mma_op(d[2 * ntp],     ah, b[4 * q],     b[4 * q + 1]);
                mma_op(d[2 * ntp + 1], ah, b[4 * q + 2], b[4 * q + 3]);
            }
        }
    }

    // epilogue: + bias, store to g_PE
    int row0 = vbase + mrow + g;
#pragma unroll
    for (int j = 0; j < 16; j++) {
        float2 bb = *(const float2*)(b1s + 8 * j + c2);
        float* o0 = g_PE + (size_t)row0 * HD + 8 * j + c2;
        *(float2*)o0 = make_float2(d[j][0] + bb.x, d[j][1] + bb.y);
        *(float2*)(o0 + 8 * HD) = make_float2(d[j][2] + bb.x, d[j][3] + bb.y);
    }
}

// =========================================================================
// Kernel 2 (scan): persistent register-fragment RNN, single-fp16 states
// and weights (3 tile-mults/step), software-pipelined PE gather, fused
// u/v head. 128 CTAs x 256 thr (2 warps/SMSP).
// =========================================================================
#define S_W1  0
#define S_WI  TILE_B
#define S_W2  (2*TILE_B)
#define S_B2  (3*TILE_B)
#define S_PW  (3*TILE_B + 512)
#define SCAN_SMEM (3*TILE_B + 512 + 1024)

__global__ void __launch_bounds__(256, 1) scan_hmma_kernel(
    const int* __restrict__ x,
    const float* __restrict__ b_ih, const float* __restrict__ b_hh,
    const float* __restrict__ pred_W)
{
    extern __shared__ char smem[];
    const int tid = threadIdx.x;
    const int l = tid & 31, wid = tid >> 5;
    uint32_t sb = smem_u32(smem);

    // vectorized copy of pre-converted Wh1 / Wi2 / Wh2 tiles
    {
        uint4* wdst = (uint4*)(smem + S_W1);
        for (int i = tid; i < 3 * TILE_U4; i += 256) {
            int t = i / TILE_U4, j = i - t * TILE_U4;
            wdst[t * TILE_U4 + j] = g_Wt[1 + t][j];
        }
    }
    if (tid < 128) ((float*)(smem + S_B2))[tid] = b_ih[128 + tid] + b_hh[128 + tid];
    if (tid < 256) ((float*)(smem + S_PW))[tid] = pred_W[tid];
    __syncthreads();

    const int lrowB = ((l >> 4) & 1) * 8 + (l & 7);
    const int lkofB = 8 * ((l >> 3) & 1);
    const int g = l >> 2, c2 = (l & 3) * 2;
    const int mrow = wid * 16;
    const size_t rowA = (size_t)(blockIdx.x * 128 + mrow + g);
    const float* b2s = (const float*)(smem + S_B2);
    const float* pw1 = (const float*)(smem + S_PW);
    const float* pw2 = pw1 + 128;

    const int* xa = x + rowA * SLEN;            // tokens of seq rowA
    const int* xb = x + (rowA + 8) * SLEN;      // tokens of seq rowA+8

    uint32_t h1h[32], h2h[32];
#pragma unroll
    for (int i = 0; i < 32; i++) { h1h[i] = 0; h2h[i] = 0; }

    float d[16][4];
    float2 pra[16], prb[16];                     // prefetched PE rows for step t
    float u_a = 0.f, v_a = 0.f, u_b = 0.f, v_b = 0.f;

    // prefetch t=0 PE rows into registers
    {
        int tokA = xa[0], tokB = xb[0];
        const float* pa = g_PE + (size_t)tokA * HD;
        const float* pb = g_PE + (size_t)tokB * HD;
#pragma unroll
        for (int j = 0; j < 16; j++) {
            pra[j] = *(const float2*)(pa + 8 * j + c2);
            prb[j] = *(const float2*)(pb + 8 * j + c2);
        }
    }

#pragma unroll 1
    for (int t = 0; t < SLEN; t++) {
        // ---- D init from prefetched registers ----
#pragma unroll
        for (int j = 0; j < 16; j++) {
            d[j][0] = pra[j].x; d[j][1] = pra[j].y;
            d[j][2] = prb[j].x; d[j][3] = prb[j].y;
        }
        // ---- issue next step's gather now; drains during the MMA passes ----
        if (t + 1 < SLEN) {
            int tokA = xa[t + 1], tokB = xb[t + 1];
            const float* pa = g_PE + (size_t)tokA * HD;
            const float* pb = g_PE + (size_t)tokB * HD;
#pragma unroll
            for (int j = 0; j < 16; j++) {
                pra[j] = *(const float2*)(pa + 8 * j + c2);
                prb[j] = *(const float2*)(pb + 8 * j + c2);
            }
        }

        // ---- layer 1: D += h1 x Wh1 ----
        mma_pass1(d, h1h, sb + S_W1, lrowB, lkofB);

        // ---- epilogue 1: h1 = fp16(relu(D)) ----
#pragma unroll
        for (int kc = 0; kc < 8; kc++) {
            int j0 = 2 * kc, j1 = 2 * kc + 1;
            h1h[4*kc+0] = pack2h(fmaxf(d[j0][0], 0.f), fmaxf(d[j0][1], 0.f));
            h1h[4*kc+1] = pack2h(fmaxf(d[j0][2], 0.f), fmaxf(d[j0][3], 0.f));
            h1h[4*kc+2] = pack2h(fmaxf(d[j1][0], 0.f), fmaxf(d[j1][1], 0.f));
            h1h[4*kc+3] = pack2h(fmaxf(d[j1][2], 0.f), fmaxf(d[j1][3], 0.f));
        }

        // ---- layer 2: D = h1 x Wi2 + h2 x Wh2 ----
#pragma unroll
        for (int j = 0; j < 16; j++)
#pragma unroll
            for (int q = 0; q < 4; q++) d[j][q] = 0.f;
        mma_pass1(d, h1h, sb + S_WI, lrowB, lkofB);
        mma_pass1(d, h2h, sb + S_W2, lrowB, lkofB);

        // ---- epilogue 2: h2 = fp16(relu(D + b2)); fused u/v head at last t ----
#pragma unroll
        for (int kc = 0; kc < 8; kc++) {
            int j0 = 2 * kc, j1 = 2 * kc + 1;
            float2 bb0 = *(const float2*)(b2s + 8 * j0 + c2);
            float2 bb1 = *(const float2*)(b2s + 8 * j1 + c2);
            float f00 = fmaxf(d[j0][0] + bb0.x, 0.f), f01 = fmaxf(d[j0][1] + bb0.y, 0.f);
            float f02 = fmaxf(d[j0][2] + bb0.x, 0.f), f03 = fmaxf(d[j0][3] + bb0.y, 0.f);
            float f10 = fmaxf(d[j1][0] + bb1.x, 0.f), f11 = fmaxf(d[j1][1] + bb1.y, 0.f);
            float f12 = fmaxf(d[j1][2] + bb1.x, 0.f), f13 = fmaxf(d[j1][3] + bb1.y, 0.f);
            h2h[4*kc+0] = pack2h(f00, f01);
            h2h[4*kc+1] = pack2h(f02, f03);
            h2h[4*kc+2] = pack2h(f10, f11);
            h2h[4*kc+3] = pack2h(f12, f13);
            if (t == SLEN - 1) {
                int c0 = 8 * j0 + c2, c1 = 8 * j1 + c2;
                u_a += pw1[c0] * f00 + pw1[c0 + 1] * f01 + pw1[c1] * f10 + pw1[c1 + 1] * f11;
                u_b += pw1[c0] * f02 + pw1[c0 + 1] * f03 + pw1[c1] * f12 + pw1[c1 + 1] * f13;
                v_a += pw2[c0] * f00 + pw2[c0 + 1] * f01 + pw2[c1] * f10 + pw2[c1 + 1] * f11;
                v_b += pw2[c0] * f02 + pw2[c0 + 1] * f03 + pw2[c1] * f12 + pw2[c1 + 1] * f13;
            }
        }
    }

    // quad reduction over the 4 lanes sharing each row (c2 = 0,2,4,6)
#pragma unroll
    for (int o = 1; o <= 2; o <<= 1) {
        u_a += __shfl_xor_sync(0xffffffffu, u_a, o);
        u_b += __shfl_xor_sync(0xffffffffu, u_b, o);
        v_a += __shfl_xor_sync(0xffffffffu, v_a, o);
        v_b += __shfl_xor_sync(0xffffffffu, v_b, o);
    }
    if ((l & 3) == 0) {
        g_u[rowA] = u_a;     g_v[rowA] = v_a;
        g_u[rowA + 8] = u_b; g_v[rowA + 8] = v_b;
    }
}

// =========================================================================
// Kernel 3: out = u - 2v + rowsum(v) + colsum(v) + pred_b
// grid NB x 1024 thr; g_u hoisted; warp shuffle reductions; pitch-65 smem.
// =========================================================================
__global__ void __launch_bounds__(1024, 1) reduce2_kernel(
    const float* __restrict__ pred_b, float* __restrict__ out)
{
    __shared__ float vs[64 * 65];
    __shared__ float RS[64], CS[64];
    const int b = blockIdx.x, tid = threadIdx.x;
    const int w = tid >> 5, l = tid & 31;

    // hoist g_u loads so their latency overlaps the staging + reductions
    float u0 = g_u[b * 4096 + tid];
    float u1 = g_u[b * 4096 + tid + 1024];
    float u2 = g_u[b * 4096 + tid + 2048];
    float u3 = g_u[b * 4096 + tid + 3072];

    for (int i = tid; i < 4096; i += 1024)
        vs[(i >> 6) * 65 + (i & 63)] = g_v[b * 4096 + i];
    __syncthreads();

    // row sums: warp w -> rows w, w+32
    float r0 = vs[w * 65 + l] + vs[w * 65 + l + 32];
    float r1 = vs[(w + 32) * 65 + l] + vs[(w + 32) * 65 + l + 32];
    // col sums: warp w -> cols w, w+32 (pitch 65 => conflict-free)
    float q0 = vs[l * 65 + w] + vs[(l + 32) * 65 + w];
    float q1 = vs[l * 65 + w + 32] + vs[(l + 32) * 65 + w + 32];
#pragma unroll
    for (int o = 16; o; o >>= 1) {
        r0 += __shfl_xor_sync(0xffffffffu, r0, o);
        r1 += __shfl_xor_sync(0xffffffffu, r1, o);
        q0 += __shfl_xor_sync(0xffffffffu, q0, o);
        q1 += __shfl_xor_sync(0xffffffffu, q1, o);
    }
    if (l == 0) { RS[w] = r0; RS[w + 32] = r1; CS[w] = q0; CS[w + 32] = q1; }
    __syncthreads();

    float pb = pred_b[0];
    float uu[4] = {u0, u1, u2, u3};
#pragma unroll
    for (int p = 0; p < 4; p++) {
        int i = tid + 1024 * p;
        int r = i >> 6, c = i & 63;
        out[b * 4096 + i] =
            uu[p] - 2.f * vs[r * 65 + c] + RS[r] + CS[c] + pb;
    }
}

// =========================================================================
extern "C" void kernel_launch(void* const* d_in, const int* in_sizes, int n_in,
                              void* d_out, int out_size)
{
    const int*   x      = (const int*)  d_in[0];
    const float* embed  = (const float*)d_in[1];
    const float* W_ih   = (const float*)d_in[2];
    const float* W_hh   = (const float*)d_in[3];
    const float* b_ih   = (const float*)d_in[4];
    const float* b_hh   = (const float*)d_in[5];
    const float* pred_W = (const float*)d_in[6];
    const float* pred_b = (const float*)d_in[7];
    float* out = (float*)d_out;

    cudaFuncSetAttribute(pe_hmma_kernel,   cudaFuncAttributeMaxDynamicSharedMemorySize, PROJ_SMEM);
    cudaFuncSetAttribute(scan_hmma_kernel, cudaFuncAttributeMaxDynamicSharedMemorySize, SCAN_SMEM);

    prep_kernel<<<256, 256>>>(W_ih, W_hh);
    pe_hmma_kernel<<<NVPAD / 128, 256, PROJ_SMEM>>>(embed, b_ih, b_hh);
    scan_hmma_kernel<<<128, 256, SCAN_SMEM>>>(x, b_ih, b_hh, pred_W);
    reduce2_kernel<<<NB, 1024>>>(pred_b, out);
}

// round 16
// speedup vs baseline: 1.1554x; 1.0119x over previous
#include <cuda_runtime.h>
#include <cuda_fp16.h>
#include <cstdint>

#define NB 4
#define NR 64
#define NC 64
#define NSEQ 16384
#define SLEN 32
#define HD 128
#define NV 30000
#define NVPAD 30080             // 235 * 128
#define PKW 136                 // fp16 pitch of weight/A tiles (272B, LDSM conflict-free)
#define TILE_B (128*PKW*2)      // 34816 bytes per 128x128 fp16 tile
#define TILE_U4 (TILE_B/16)     // 2176 uint4 per 128-row tile

// ---------------- device scratch ----------------
__device__ float g_PE[(size_t)NVPAD * HD];     // 15.4 MB: embed @ Wi1^T + b1 (L2-resident)
__device__ uint4 g_Wt[4][TILE_U4];             // fp16 pitched tiles: Wi1, Wh1, Wi2, Wh2
__device__ float g_u[NSEQ];
__device__ float g_v[NSEQ];

// ================= helpers =================
__device__ __forceinline__ uint32_t smem_u32(const void* p) {
    uint32_t a;
    asm("{ .reg .u64 t; cvta.to.shared.u64 t, %1; cvt.u32.u64 %0, t; }" : "=r"(a) : "l"(p));
    return a;
}
__device__ __forceinline__ void ldsm_x4(uint32_t* r, uint32_t addr) {
    asm volatile("ldmatrix.sync.aligned.m8n8.x4.shared.b16 {%0,%1,%2,%3}, [%4];"
        : "=r"(r[0]), "=r"(r[1]), "=r"(r[2]), "=r"(r[3]) : "r"(addr));
}
__device__ __forceinline__ void mma_op(float* d, const uint32_t* a, uint32_t b0, uint32_t b1) {
    asm volatile("mma.sync.aligned.m16n8k16.row.col.f32.f16.f16.f32 "
        "{%0,%1,%2,%3}, {%4,%5,%6,%7}, {%8,%9}, {%0,%1,%2,%3};"
        : "+f"(d[0]), "+f"(d[1]), "+f"(d[2]), "+f"(d[3])
        : "r"(a[0]), "r"(a[1]), "r"(a[2]), "r"(a[3]), "r"(b0), "r"(b1));
}
// mma with explicit (separate) C operand — fuses the accumulator init
__device__ __forceinline__ void mma_op_c(float* d, const uint32_t* a, uint32_t b0, uint32_t b1,
                                         float c0, float c1, float c2_, float c3_) {
    asm volatile("mma.sync.aligned.m16n8k16.row.col.f32.f16.f16.f32 "
        "{%0,%1,%2,%3}, {%4,%5,%6,%7}, {%8,%9}, {%10,%11,%12,%13};"
        : "=f"(d[0]), "=f"(d[1]), "=f"(d[2]), "=f"(d[3])
        : "r"(a[0]), "r"(a[1]), "r"(a[2]), "r"(a[3]), "r"(b0), "r"(b1),
          "f"(c0), "f"(c1), "f"(c2_), "f"(c3_));
}
// pack (f0,f1) into fp16 pair (f0 -> lo) using single-instr packed cvt
__device__ __forceinline__ uint32_t pack2h(float f0, float f1) {
    uint32_t r;
    asm("cvt.rn.f16x2.f32 %0, %1, %2;" : "=r"(r) : "f"(f1), "f"(f0));
    return r;
}

// Single-A pass: D += A x B(smem tile at wb)
__device__ __forceinline__ void mma_pass1(float (*d)[4], const uint32_t* a,
                                          uint32_t wb, int lrowB, int lkofB)
{
#pragma unroll
    for (int kc = 0; kc < 8; kc++) {
#pragma unroll
        for (int half = 0; half < 2; half++) {
            uint32_t b[16];
#pragma unroll
            for (int q = 0; q < 4; q++) {
                int ntp = half * 4 + q;
                ldsm_x4(b + 4 * q, wb + (uint32_t)(((ntp * 16 + lrowB) * PKW + kc * 16 + lkofB) * 2));
            }
#pragma unroll
            for (int q = 0; q < 4; q++) {
                int ntp = half * 4 + q;
                mma_op(d[2 * ntp],     a + 4 * kc, b[4 * q],     b[4 * q + 1]);
                mma_op(d[2 * ntp + 1], a + 4 * kc, b[4 * q + 2], b[4 * q + 3]);
            }
        }
    }
}

// Pass with D initialized through C at kc==0 from prefetched PE rows:
// D(kc0) = A0 x B + [pra | prb]
__device__ __forceinline__ void mma_pass1_pr(float (*d)[4], const uint32_t* a,
                                             uint32_t wb, int lrowB, int lkofB,
                                             const float2* pra, const float2* prb)
{
#pragma unroll
    for (int kc = 0; kc < 8; kc++) {
#pragma unroll
        for (int half = 0; half < 2; half++) {
            uint32_t b[16];
#pragma unroll
            for (int q = 0; q < 4; q++) {
                int ntp = half * 4 + q;
                ldsm_x4(b + 4 * q, wb + (uint32_t)(((ntp * 16 + lrowB) * PKW + kc * 16 + lkofB) * 2));
            }
#pragma unroll
            for (int q = 0; q < 4; q++) {
                int ntp = half * 4 + q;
                int j0 = 2 * ntp, j1 = 2 * ntp + 1;
                if (kc == 0) {
                    mma_op_c(d[j0], a, b[4 * q],     b[4 * q + 1],
                             pra[j0].x, pra[j0].y, prb[j0].x, prb[j0].y);
                    mma_op_c(d[j1], a, b[4 * q + 2], b[4 * q + 3],
                             pra[j1].x, pra[j1].y, prb[j1].x, prb[j1].y);
                } else {
                    mma_op(d[j0], a + 4 * kc, b[4 * q],     b[4 * q + 1]);
                    mma_op(d[j1], a + 4 * kc, b[4 * q + 2], b[4 * q + 3]);
                }
            }
        }
    }
}

// Pass with D initialized through C at kc==0 from per-column bias (smem):
// D(kc0) = A0 x B + bias  (bias broadcast across both m-rows)
__device__ __forceinline__ void mma_pass1_bias(float (*d)[4], const uint32_t* a,
                                               uint32_t wb, int lrowB, int lkofB,
                                               const float* b2s, int c2)
{
#pragma unroll
    for (int kc = 0; kc < 8; kc++) {
#pragma unroll
        for (int half = 0; half < 2; half++) {
            uint32_t b[16];
#pragma unroll
            for (int q = 0; q < 4; q++) {
                int ntp = half * 4 + q;
                ldsm_x4(b + 4 * q, wb + (uint32_t)(((ntp * 16 + lrowB) * PKW + kc * 16 + lkofB) * 2));
            }
#pragma unroll
            for (int q = 0; q < 4; q++) {
                int ntp = half * 4 + q;
                int j0 = 2 * ntp, j1 = 2 * ntp + 1;
                if (kc == 0) {
                    float2 bb0 = *(const float2*)(b2s + 8 * j0 + c2);
                    float2 bb1 = *(const float2*)(b2s + 8 * j1 + c2);
                    mma_op_c(d[j0], a, b[4 * q],     b[4 * q + 1],
                             bb0.x, bb0.y, bb0.x, bb0.y);
                    mma_op_c(d[j1], a, b[4 * q + 2], b[4 * q + 3],
                             bb1.x, bb1.y, bb1.x, bb1.y);
                } else {
                    mma_op(d[j0], a + 4 * kc, b[4 * q],     b[4 * q + 1]);
                    mma_op(d[j1], a + 4 * kc, b[4 * q + 2], b[4 * q + 3]);
                }
            }
        }
    }
}

// =========================================================================
// Kernel 0 (prep): convert the 4 weight matrices to fp16 pitched tiles.
// tiles: [0]=Wi1, [1]=Wh1, [2]=Wi2, [3]=Wh2
// =========================================================================
__global__ void __launch_bounds__(256, 8) prep_kernel(
    const float* __restrict__ W_ih, const float* __restrict__ W_hh)
{
    int idx = blockIdx.x * 256 + threadIdx.x;
    if (idx >= 4 * 16384) return;
    int tile = idx >> 14, i = idx & 16383;
    int n = i >> 7, k = i & 127;
    const float* src = (tile == 0) ? W_ih : (tile == 1) ? W_hh
                     : (tile == 2) ? (W_ih + 16384) : (W_hh + 16384);
    reinterpret_cast<__half*>(g_Wt[tile])[n * PKW + k] = __float2half_rn(src[i]);
}

// =========================================================================
// Kernel 1 (PE): PE[v][h] = embed[v] @ Wi1^T + (bi1+bh1)
// 235 CTAs x 256 thr, 128-row tiles, single fp16 A (no compensation).
// =========================================================================
#define P_A   0
#define P_B   TILE_B
#define P_B1  (2*TILE_B)
#define PROJ_SMEM (2*TILE_B + 512)

__global__ void __launch_bounds__(256, 2) pe_hmma_kernel(
    const float* __restrict__ embed,
    const float* __restrict__ b_ih, const float* __restrict__ b_hh)
{
    extern __shared__ char smem[];
    const int tid = threadIdx.x;
    const int l = tid & 31, wid = tid >> 5;
    uint32_t sb = smem_u32(smem);

    const int vbase = blockIdx.x * 128;

    // vectorized copy of pre-converted Wi1 tile
    {
        uint4* wdst = (uint4*)(smem + P_B);
        for (int i = tid; i < TILE_U4; i += 256) wdst[i] = g_Wt[0][i];
    }
    if (tid < 128) ((float*)(smem + P_B1))[tid] = b_ih[tid] + b_hh[tid];
    const float* b1s = (const float*)(smem + P_B1);

    // A tile = 128 consecutive vocab embedding rows (guarded), single fp16
    for (int i = tid; i < 128 * 32; i += 256) {
        int r = i >> 5, c = i & 31;
        int vr = vbase + r; if (vr >= NV) vr = NV - 1;
        float4 v = ((const float4*)embed)[(size_t)vr * 32 + c];
        uint32_t off = (uint32_t)(r * PKW + 4 * c) * 2;
        *(uint2*)(smem + P_A + off) = make_uint2(pack2h(v.x, v.y), pack2h(v.z, v.w));
    }
    __syncthreads();

    const int mrow = wid * 16;
    const int lrowB = ((l >> 4) & 1) * 8 + (l & 7);
    const int lkofB = 8 * ((l >> 3) & 1);
    const int lrowA = ((l >> 3) & 1) * 8 + (l & 7);
    const int lkofA = 8 * ((l >> 4) & 1);
    const int g = l >> 2, c2 = (l & 3) * 2;

    float d[16][4];
#pragma unroll
    for (int j = 0; j < 16; j++)
#pragma unroll
        for (int q = 0; q < 4; q++) d[j][q] = 0.f;

    // single pass: D = A x B
#pragma unroll
    for (int kc = 0; kc < 8; kc++) {
        uint32_t ah[4];
        ldsm_x4(ah, sb + P_A + (uint32_t)(((mrow + lrowA) * PKW + kc * 16 + lkofA) * 2));
#pragma unroll
        for (int half = 0; half < 2; half++) {
            uint32_t b[16];
#pragma unroll
            for (int q = 0; q < 4; q++) {
                int ntp = half * 4 + q;
                ldsm_x4(b + 4 * q, sb + P_B + (uint32_t)(((ntp * 16 + lrowB) * PKW + kc * 16 + lkofB) * 2));
            }
#pragma unroll
            for (int q = 0; q < 4; q++) {
                int ntp = half * 4 + q;
                mma_op(d[2 * ntp],     ah, b[4 * q],     b[4 * q + 1]);
                mma_op(d[2 * ntp + 1], ah, b[4 * q + 2], b[4 * q + 3]);
            }
        }
    }

    // epilogue: + bias, store to g_PE
    int row0 = vbase + mrow + g;
#pragma unroll
    for (int j = 0; j < 16; j++) {
        float2 bb = *(const float2*)(b1s + 8 * j + c2);
        float* o0 = g_PE + (size_t)row0 * HD + 8 * j + c2;
        *(float2*)o0 = make_float2(d[j][0] + bb.x, d[j][1] + bb.y);
        *(float2*)(o0 + 8 * HD) = make_float2(d[j][2] + bb.x, d[j][3] + bb.y);
    }
}

// =========================================================================
// Kernel 2 (scan): persistent register-fragment RNN, single-fp16 states
// and weights (3 tile-mults/step), D-init fused into MMA C operand,
// software-pipelined PE gather, fused u/v head. 128 CTAs x 256 thr.
// =========================================================================
#define S_W1  0
#define S_WI  TILE_B
#define S_W2  (2*TILE_B)
#define S_B2  (3*TILE_B)
#define S_PW  (3*TILE_B + 512)
#define SCAN_SMEM (3*TILE_B + 512 + 1024)

__global__ void __launch_bounds__(256, 1) scan_hmma_kernel(
    const int* __restrict__ x,
    const float* __restrict__ b_ih, const float* __restrict__ b_hh,
    const float* __restrict__ pred_W)
{
    extern __shared__ char smem[];
    const int tid = threadIdx.x;
    const int l = tid & 31, wid = tid >> 5;
    uint32_t sb = smem_u32(smem);

    // vectorized copy of pre-converted Wh1 / Wi2 / Wh2 tiles
    {
        uint4* wdst = (uint4*)(smem + S_W1);
        for (int i = tid; i < 3 * TILE_U4; i += 256) {
            int t = i / TILE_U4, j = i - t * TILE_U4;
            wdst[t * TILE_U4 + j] = g_Wt[1 + t][j];
        }
    }
    if (tid < 128) ((float*)(smem + S_B2))[tid] = b_ih[128 + tid] + b_hh[128 + tid];
    if (tid < 256) ((float*)(smem + S_PW))[tid] = pred_W[tid];
    __syncthreads();

    const int lrowB = ((l >> 4) & 1) * 8 + (l & 7);
    const int lkofB = 8 * ((l >> 3) & 1);
    const int g = l >> 2, c2 = (l & 3) * 2;
    const int mrow = wid * 16;
    const size_t rowA = (size_t)(blockIdx.x * 128 + mrow + g);
    const float* b2s = (const float*)(smem + S_B2);
    const float* pw1 = (const float*)(smem + S_PW);
    const float* pw2 = pw1 + 128;

    const int* xa = x + rowA * SLEN;            // tokens of seq rowA
    const int* xb = x + (rowA + 8) * SLEN;      // tokens of seq rowA+8

    uint32_t h1h[32], h2h[32];
#pragma unroll
    for (int i = 0; i < 32; i++) { h1h[i] = 0; h2h[i] = 0; }

    float d[16][4];
    float2 pra[16], prb[16];                     // prefetched PE rows for step t
    float u_a = 0.f, v_a = 0.f, u_b = 0.f, v_b = 0.f;

    // prefetch t=0 PE rows into registers
    {
        int tokA = xa[0], tokB = xb[0];
        const float* pa = g_PE + (size_t)tokA * HD;
        const float* pb = g_PE + (size_t)tokB * HD;
#pragma unroll
        for (int j = 0; j < 16; j++) {
            pra[j] = *(const float2*)(pa + 8 * j + c2);
            prb[j] = *(const float2*)(pb + 8 * j + c2);
        }
    }

#pragma unroll 1
    for (int t = 0; t < SLEN; t++) {
        // ---- layer 1: D = pr + h1 x Wh1 (init via C operand at kc==0) ----
        mma_pass1_pr(d, h1h, sb + S_W1, lrowB, lkofB, pra, prb);

        // ---- pra/prb consumed: issue next step's gather now ----
        if (t + 1 < SLEN) {
            int tokA = xa[t + 1], tokB = xb[t + 1];
            const float* pa = g_PE + (size_t)tokA * HD;
            const float* pb = g_PE + (size_t)tokB * HD;
#pragma unroll
            for (int j = 0; j < 16; j++) {
                pra[j] = *(const float2*)(pa + 8 * j + c2);
                prb[j] = *(const float2*)(pb + 8 * j + c2);
            }
        }

        // ---- epilogue 1: h1 = fp16(relu(D)) ----
#pragma unroll
        for (int kc = 0; kc < 8; kc++) {
            int j0 = 2 * kc, j1 = 2 * kc + 1;
            h1h[4*kc+0] = pack2h(fmaxf(d[j0][0], 0.f), fmaxf(d[j0][1], 0.f));
            h1h[4*kc+1] = pack2h(fmaxf(d[j0][2], 0.f), fmaxf(d[j0][3], 0.f));
            h1h[4*kc+2] = pack2h(fmaxf(d[j1][0], 0.f), fmaxf(d[j1][1], 0.f));
            h1h[4*kc+3] = pack2h(fmaxf(d[j1][2], 0.f), fmaxf(d[j1][3], 0.f));
        }

        // ---- layer 2: D = b2 + h1 x Wi2 + h2 x Wh2 (bias via C at kc==0) ----
        mma_pass1_bias(d, h1h, sb + S_WI, lrowB, lkofB, b2s, c2);
        mma_pass1(d, h2h, sb + S_W2, lrowB, lkofB);

        // ---- epilogue 2: h2 = fp16(relu(D)); fused u/v head at last t ----
#pragma unroll
        for (int kc = 0; kc < 8; kc++) {
            int j0 = 2 * kc, j1 = 2 * kc + 1;
            float f00 = fmaxf(d[j0][0], 0.f), f01 = fmaxf(d[j0][1], 0.f);
            float f02 = fmaxf(d[j0][2], 0.f), f03 = fmaxf(d[j0][3], 0.f);
            float f10 = fmaxf(d[j1][0], 0.f), f11 = fmaxf(d[j1][1], 0.f);
            float f12 = fmaxf(d[j1][2], 0.f), f13 = fmaxf(d[j1][3], 0.f);
            h2h[4*kc+0] = pack2h(f00, f01);
            h2h[4*kc+1] = pack2h(f02, f03);
            h2h[4*kc+2] = pack2h(f10, f11);
            h2h[4*kc+3] = pack2h(f12, f13);
            if (t == SLEN - 1) {
                int c0 = 8 * j0 + c2, c1 = 8 * j1 + c2;
                u_a += pw1[c0] * f00 + pw1[c0 + 1] * f01 + pw1[c1] * f10 + pw1[c1 + 1] * f11;
                u_b += pw1[c0] * f02 + pw1[c0 + 1] * f03 + pw1[c1] * f12 + pw1[c1 + 1] * f13;
                v_a += pw2[c0] * f00 + pw2[c0 + 1] * f01 + pw2[c1] * f10 + pw2[c1 + 1] * f11;
                v_b += pw2[c0] * f02 + pw2[c0 + 1] * f03 + pw2[c1] * f12 + pw2[c1 + 1] * f13;
            }
        }
    }

    // quad reduction over the 4 lanes sharing each row (c2 = 0,2,4,6)
#pragma unroll
    for (int o = 1; o <= 2; o <<= 1) {
        u_a += __shfl_xor_sync(0xffffffffu, u_a, o);
        u_b += __shfl_xor_sync(0xffffffffu, u_b, o);
        v_a += __shfl_xor_sync(0xffffffffu, v_a, o);
        v_b += __shfl_xor_sync(0xffffffffu, v_b, o);
    }
    if ((l & 3) == 0) {
        g_u[rowA] = u_a;     g_v[rowA] = v_a;
        g_u[rowA + 8] = u_b; g_v[rowA + 8] = v_b;
    }
}

// =========================================================================
// Kernel 3: out = u - 2v + rowsum(v) + colsum(v) + pred_b
// grid NB x 1024 thr; g_u hoisted; warp shuffle reductions; pitch-65 smem.
// =========================================================================
__global__ void __launch_bounds__(1024, 1) reduce2_kernel(
    const float* __restrict__ pred_b, float* __restrict__ out)
{
    __shared__ float vs[64 * 65];
    __shared__ float RS[64], CS[64];
    const int b = blockIdx.x, tid = threadIdx.x;
    const int w = tid >> 5, l = tid & 31;

    // hoist g_u loads so their latency overlaps the staging + reductions
    float u0 = g_u[b * 4096 + tid];
    float u1 = g_u[b * 4096 + tid + 1024];
    float u2 = g_u[b * 4096 + tid + 2048];
    float u3 = g_u[b * 4096 + tid + 3072];

    for (int i = tid; i < 4096; i += 1024)
        vs[(i >> 6) * 65 + (i & 63)] = g_v[b * 4096 + i];
    __syncthreads();

    // row sums: warp w -> rows w, w+32
    float r0 = vs[w * 65 + l] + vs[w * 65 + l + 32];
    float r1 = vs[(w + 32) * 65 + l] + vs[(w + 32) * 65 + l + 32];
    // col sums: warp w -> cols w, w+32 (pitch 65 => conflict-free)
    float q0 = vs[l * 65 + w] + vs[(l + 32) * 65 + w];
    float q1 = vs[l * 65 + w + 32] + vs[(l + 32) * 65 + w + 32];
#pragma unroll
    for (int o = 16; o; o >>= 1) {
        r0 += __shfl_xor_sync(0xffffffffu, r0, o);
        r1 += __shfl_xor_sync(0xffffffffu, r1, o);
        q0 += __shfl_xor_sync(0xffffffffu, q0, o);
        q1 += __shfl_xor_sync(0xffffffffu, q1, o);
    }
    if (l == 0) { RS[w] = r0; RS[w + 32] = r1; CS[w] = q0; CS[w + 32] = q1; }
    __syncthreads();

    float pb = pred_b[0];
    float uu[4] = {u0, u1, u2, u3};
#pragma unroll
    for (int p = 0; p < 4; p++) {
        int i = tid + 1024 * p;
        int r = i >> 6, c = i & 63;
        out[b * 4096 + i] =
            uu[p] - 2.f * vs[r * 65 + c] + RS[r] + CS[c] + pb;
    }
}

// =========================================================================
extern "C" void kernel_launch(void* const* d_in, const int* in_sizes, int n_in,
                              void* d_out, int out_size)
{
    const int*   x      = (const int*)  d_in[0];
    const float* embed  = (const float*)d_in[1];
    const float* W_ih   = (const float*)d_in[2];
    const float* W_hh   = (const float*)d_in[3];
    const float* b_ih   = (const float*)d_in[4];
    const float* b_hh   = (const float*)d_in[5];
    const float* pred_W = (const float*)d_in[6];
    const float* pred_b = (const float*)d_in[7];
    float* out = (float*)d_out;

    cudaFuncSetAttribute(pe_hmma_kernel,   cudaFuncAttributeMaxDynamicSharedMemorySize, PROJ_SMEM);
    cudaFuncSetAttribute(scan_hmma_kernel, cudaFuncAttributeMaxDynamicSharedMemorySize, SCAN_SMEM);

    prep_kernel<<<256, 256>>>(W_ih, W_hh);
    pe_hmma_kernel<<<NVPAD / 128, 256, PROJ_SMEM>>>(embed, b_ih, b_hh);
    scan_hmma_kernel<<<128, 256, SCAN_SMEM>>>(x, b_ih, b_hh, pred_W);
    reduce2_kernel<<<NB, 1024>>>(pred_b, out);
}